// round 12
// baseline (speedup 1.0000x reference)
#include <cuda_runtime.h>
#include <cstdint>

#define NPTS 8192
#define NS   2048
#define NK   32
#define NB   4
#define MPB  65536              /* NK*NS per batch */
#define FSZ  (NB*64*MPB)        /* 16.7M floats per feature buffer */
#define NPB  1024               /* stats partial blocks (4*256) */

__device__ float g_y0[FSZ];
__device__ float g_t1[FSZ];
__device__ float g_t2[FSZ];
__device__ float g_x1[FSZ];
__device__ float g_nxyz[NB*NS*3];
__device__ int   g_idx[NB*NK*NS];
__device__ float g_ps[64*2048];
__device__ float g_pq[64*2048];
__device__ float g_aff[5*128];

static __device__ __forceinline__ unsigned long long pk2(float lo, float hi){
    unsigned long long r; asm("mov.b64 %0,{%1,%2};" : "=l"(r) : "f"(lo), "f"(hi)); return r;
}
static __device__ __forceinline__ void upk2(unsigned long long v, float& lo, float& hi){
    asm("mov.b64 {%0,%1},%2;" : "=f"(lo), "=f"(hi) : "l"(v));
}
static __device__ __forceinline__ void upk2u(unsigned long long v, unsigned& lo, unsigned& hi){
    asm("mov.b64 {%0,%1},%2;" : "=r"(lo), "=r"(hi) : "l"(v));
}
static __device__ __forceinline__ unsigned long long f2fma(unsigned long long a, unsigned long long b, unsigned long long c){
    unsigned long long r; asm("fma.rn.f32x2 %0,%1,%2,%3;" : "=l"(r) : "l"(a), "l"(b), "l"(c)); return r;
}
static __device__ __forceinline__ unsigned long long f2mul(unsigned long long a, unsigned long long b){
    unsigned long long r; asm("mul.rn.f32x2 %0,%1,%2;" : "=l"(r) : "l"(a), "l"(b)); return r;
}
static __device__ __forceinline__ unsigned long long f2add(unsigned long long a, unsigned long long b){
    unsigned long long r; asm("add.rn.f32x2 %0,%1,%2;" : "=l"(r) : "l"(a), "l"(b)); return r;
}
static __device__ __forceinline__ unsigned long long f2sub(unsigned long long a, unsigned long long b){
    unsigned long long r; asm("sub.rn.f32x2 %0,%1,%2;" : "=l"(r) : "l"(a), "l"(b)); return r;
}
static __device__ __forceinline__ unsigned smem_u32(const void* p){
    unsigned a; asm("{ .reg .u64 t; cvta.to.shared.u64 t, %1; cvt.u32.u64 %0, t; }" : "=r"(a) : "l"(p));
    return a;
}
static __device__ __forceinline__ unsigned ctarank(){
    unsigned r; asm("mov.u32 %0, %%cluster_ctarank;" : "=r"(r)); return r;
}
static __device__ __forceinline__ unsigned mapa_u32(unsigned laddr, unsigned r){
    unsigned a; asm("mapa.shared::cluster.u32 %0, %1, %2;" : "=r"(a) : "r"(laddr), "r"(r)); return a;
}
static __device__ __forceinline__ void stc64(unsigned addr, unsigned long long v){
    asm volatile("st.shared::cluster.u64 [%0], %1;" :: "r"(addr), "l"(v) : "memory");
}
static __device__ __forceinline__ void stc32(unsigned addr, unsigned v){
    asm volatile("st.shared::cluster.u32 [%0], %1;" :: "r"(addr), "r"(v) : "memory");
}
static __device__ __forceinline__ void fence_cluster(){
    asm volatile("fence.acq_rel.cluster;" ::: "memory");
}

// -------- FPS v7: 4-CTA cluster per batch, DSMEM winner exchange --------
// Each CTA updates min-dists for its 2048-point quarter (exact sub/mul/add
// chain, bit-identical); full 8192-point smem mirror per CTA for coord lookup.
// Global argmax: per-CTA (key, min-orig-idx) packed as (key<<32)|~idx, pushed
// to all 4 ranks via st.shared::cluster + release-fence + seq flag; readers
// spin locally, combine with max -> exact first-occurrence semantics.
extern __shared__ float4 spts[];    // 8192 float4 = 128KB

__global__ __launch_bounds__(256, 1) __cluster_dims__(4, 1, 1)
void fps_kernel(const float* __restrict__ xyz,
                float* __restrict__ outxyz,
                float* __restrict__ nxyz)
{
    int tid = threadIdx.x, lane = tid & 31, wid = tid >> 5;   // 8 warps
    unsigned rank = ctarank();
    int b = blockIdx.x >> 2;
    const float* X = xyz + (size_t)b * 3 * NPTS;

    __shared__ unsigned swm[32];
    __shared__ unsigned swin[2];
    __shared__ unsigned long long sdata[2][4];   // [parity][src rank]
    __shared__ unsigned sseq[4];                 // per src rank seq counter

    if (tid < 4) sseq[tid] = 0u;
    if (tid < 2) swin[tid] = 0xffffffffu;
    if (tid >= 8 && tid < 32) swm[tid] = 0u;

    // full mirror of all 8192 points
#pragma unroll 4
    for (int j = 0; j < 32; ++j) {
        int n = tid + j * 256;
        spts[n] = make_float4(X[n], X[NPTS + n], X[2*NPTS + n], 0.f);
    }
    __syncthreads();

    // my quarter: 8 points per thread
    int base = (int)rank * 2048 + tid * 8;
    unsigned long long x2[4], y2[4], z2[4];
    unsigned dist[8];
#pragma unroll
    for (int p = 0; p < 4; ++p) {
        float4 A = spts[base + 2*p];
        float4 B = spts[base + 2*p + 1];
        x2[p] = pk2(A.x, B.x); y2[p] = pk2(A.y, B.y); z2[p] = pk2(A.z, B.z);
        dist[2*p] = __float_as_uint(1e10f); dist[2*p+1] = __float_as_uint(1e10f);
    }

    unsigned seq_base  = smem_u32(&sseq[0]);
    unsigned data_base = smem_u32(&sdata[0][0]);

    // all CTAs' smem init visible before any remote write
    asm volatile("barrier.cluster.arrive.aligned;" ::: "memory");
    asm volatile("barrier.cluster.wait.aligned;" ::: "memory");

    float cx = X[0], cy = X[NPTS], cz = X[2*NPTS];

    for (int it = 0; it < NS; ++it) {
        if (rank == 0 && tid == 0) {
            outxyz[(b*3 + 0)*NS + it] = cx;
            outxyz[(b*3 + 1)*NS + it] = cy;
            outxyz[(b*3 + 2)*NS + it] = cz;
            nxyz[((size_t)b*NS + it)*3 + 0] = cx;
            nxyz[((size_t)b*NS + it)*3 + 1] = cy;
            nxyz[((size_t)b*NS + it)*3 + 2] = cz;
        }
        unsigned long long cx2 = pk2(cx, cx);
        unsigned long long cy2 = pk2(cy, cy);
        unsigned long long cz2 = pk2(cz, cz);

#pragma unroll
        for (int p = 0; p < 4; ++p) {
            unsigned long long dx = f2sub(x2[p], cx2);
            unsigned long long dy = f2sub(y2[p], cy2);
            unsigned long long dz = f2sub(z2[p], cz2);
            // (dx*dx + dy*dy) + dz*dz -- lane-wise identical to scalar rounding
            unsigned long long s = f2add(f2add(f2mul(dx, dx), f2mul(dy, dy)), f2mul(dz, dz));
            unsigned slo, shi; upk2u(s, slo, shi);
            dist[2*p]   = min(dist[2*p],   slo);
            dist[2*p+1] = min(dist[2*p+1], shi);
        }
        unsigned key = 0u;
#pragma unroll
        for (int j = 0; j < 8; ++j) key = max(key, dist[j]);

        unsigned kmax = __reduce_max_sync(0xffffffffu, key);
        if (lane == 0) swm[wid] = kmax;
        __syncthreads();                               // b1
        unsigned g = __reduce_max_sync(0xffffffffu, swm[lane]);
        if (tid == 0) swin[(it + 1) & 1] = 0xffffffffu;
        if (key == g) {
            unsigned li = 0xffffffffu;
#pragma unroll
            for (int p = 3; p >= 0; --p) {             // lo overwrites hi
                if (dist[2*p+1] == g) li = (unsigned)(base + 2*p + 1);
                if (dist[2*p]   == g) li = (unsigned)(base + 2*p);
            }
            atomicMin(&swin[it & 1], li);              // CTA-local min orig idx
        }
        __syncthreads();                               // b2

        int par = it & 1;
        if (tid == 0) {
            unsigned long long pack = ((unsigned long long)g << 32)
                                    | (unsigned long long)(0xffffffffu - swin[par]);
            unsigned doff = data_base + (unsigned)(par * 4 + (int)rank) * 8u;
            unsigned soff = seq_base + rank * 4u;
#pragma unroll
            for (unsigned r = 0; r < 4; ++r) stc64(mapa_u32(doff, r), pack);
            fence_cluster();                           // data before seq
#pragma unroll
            for (unsigned r = 0; r < 4; ++r) stc32(mapa_u32(soff, r), (unsigned)(it + 1));
        }
        // spin on local seq flags (all 4 sources)
        {
            volatile unsigned* vs = (volatile unsigned*)sseq;
            unsigned tgt = (unsigned)(it + 1);
            while (vs[0] < tgt || vs[1] < tgt || vs[2] < tgt || vs[3] < tgt) { }
        }
        fence_cluster();                               // acquire data
        unsigned long long w0 = sdata[par][0], w1 = sdata[par][1];
        unsigned long long w2 = sdata[par][2], w3 = sdata[par][3];
        unsigned long long win = max(max(w0, w1), max(w2, w3));
        unsigned widx = 0xffffffffu - (unsigned)(win & 0xffffffffu);
        float4 cc = spts[widx];
        cx = cc.x; cy = cc.y; cz = cc.z;
    }
    // keep CTAs resident until all have finished reading peers' smem
    asm volatile("barrier.cluster.arrive.aligned;" ::: "memory");
    asm volatile("barrier.cluster.wait.aligned;" ::: "memory");
}

// ---------------- ball query: one warp per center ----------------
__global__ __launch_bounds__(256) void ball_kernel(const float* __restrict__ xyz,
                                                   const float* __restrict__ nxyz,
                                                   int* __restrict__ gidx)
{
    __shared__ int sbuf[8][32];
    int w = threadIdx.x >> 5, lane = threadIdx.x & 31;
    int gid = blockIdx.x * 8 + w;
    int b = gid >> 11, s = gid & 2047;
    const float* X = xyz + (size_t)b * 3 * NPTS;

    float cx = nxyz[gid*3], cy = nxyz[gid*3 + 1], cz = nxyz[gid*3 + 2];
    float cc = __fadd_rn(__fadd_rn(__fmul_rn(cx,cx), __fmul_rn(cy,cy)), __fmul_rn(cz,cz));
    const float R2 = (float)(0.1 * 0.1);

    int cnt = 0;
    for (int base = 0; base < NPTS; base += 32) {
        int n = base + lane;
        float px = X[n], py = X[NPTS + n], pz = X[2*NPTS + n];
        float pp  = __fadd_rn(__fadd_rn(__fmul_rn(px,px), __fmul_rn(py,py)), __fmul_rn(pz,pz));
        float dot = __fadd_rn(__fadd_rn(__fmul_rn(cx,px), __fmul_rn(cy,py)), __fmul_rn(cz,pz));
        float sqr = __fadd_rn(__fadd_rn(cc, pp), -__fmul_rn(2.f, dot));
        bool hit = (sqr <= R2);
        unsigned m = __ballot_sync(0xffffffffu, hit);
        if (m) {
            int rank = cnt + __popc(m & ((1u << lane) - 1u));
            if (hit && rank < 32) sbuf[w][rank] = n;
            cnt += __popc(m);
            if (cnt >= 32) break;
        }
    }
    __syncwarp();
    int first = sbuf[w][0];
    int my = (lane < cnt) ? sbuf[w][lane] : first;
    gidx[((size_t)(b*32 + lane))*2048 + s] = my;
}

// ---------------- gather + center-subtract + concat ----------------
__global__ __launch_bounds__(256) void gather_kernel(const float* __restrict__ xyz,
                                                     const float* __restrict__ pts,
                                                     const int* __restrict__ gidx,
                                                     const float* __restrict__ nxyz,
                                                     float* __restrict__ xin)
{
    int g = blockIdx.x * 256 + threadIdx.x;
    int s = g & 2047, k = (g >> 11) & 31, b = g >> 16;
    int id = gidx[((size_t)(b*32 + k))*2048 + s];
    const float* X = xyz + (size_t)b * 3 * NPTS;
    const float* P = pts + (size_t)b * 29 * NPTS;
    size_t ob = (size_t)b * 32 * MPB + (size_t)k * 2048 + s;
#pragma unroll
    for (int c = 0; c < 3; ++c)
        xin[ob + (size_t)c * MPB] = X[c*NPTS + id] - nxyz[((size_t)(b*2048 + s))*3 + c];
#pragma unroll
    for (int c = 0; c < 29; ++c)
        xin[ob + (size_t)(3 + c) * MPB] = P[c*NPTS + id];
}

// ---------------- conv v3: 256 pts/block, 8 pts/thread, fused stats ----------------
template<int CIN, bool ACT>
__global__ __launch_bounds__(256) void conv_kernel(const float* __restrict__ in,
                                                   const float* __restrict__ W,
                                                   const float* __restrict__ aff,
                                                   float* __restrict__ out,
                                                   float* __restrict__ ps,
                                                   float* __restrict__ pq)
{
    constexpr int CH = CIN / 8;
    __shared__ float sW[CIN][64];
    __shared__ float sX[2][8][256];
    __shared__ float sA[64], sD[64];
    int tid = threadIdx.x, lane = tid & 31, w = tid >> 5;
    int b = blockIdx.x >> 8, mblk = blockIdx.x & 255;
    const float* ip = in + (size_t)b * CIN * MPB + mblk * 256;

    for (int i = tid; i < CIN * 64; i += 256)
        sW[i >> 6][i & 63] = W[(i & 63) * CIN + (i >> 6)];
    if (ACT) for (int i = tid; i < CIN; i += 256) { sA[i] = aff[i]; sD[i] = aff[64 + i]; }

    float4 xa = *(const float4*)(ip + (size_t)w * MPB + lane * 4);
    float4 xb = *(const float4*)(ip + (size_t)w * MPB + 128 + lane * 4);
    float4 na, nb;
    if (CH > 1) {
        na = *(const float4*)(ip + (size_t)(8 + w) * MPB + lane * 4);
        nb = *(const float4*)(ip + (size_t)(8 + w) * MPB + 128 + lane * 4);
    }
    __syncthreads();
    {
        float4 va = xa, vb = xb;
        if (ACT) { float a = sA[w], d = sD[w];
            va.x = fmaxf(fmaf(a, va.x, d), 0.f); va.y = fmaxf(fmaf(a, va.y, d), 0.f);
            va.z = fmaxf(fmaf(a, va.z, d), 0.f); va.w = fmaxf(fmaf(a, va.w, d), 0.f);
            vb.x = fmaxf(fmaf(a, vb.x, d), 0.f); vb.y = fmaxf(fmaf(a, vb.y, d), 0.f);
            vb.z = fmaxf(fmaf(a, vb.z, d), 0.f); vb.w = fmaxf(fmaf(a, vb.w, d), 0.f); }
        *(float4*)&sX[0][w][lane * 4]       = va;
        *(float4*)&sX[0][w][128 + lane * 4] = vb;
    }
    __syncthreads();

    int og = w * 8;
    unsigned long long acc[4][8];
#pragma unroll
    for (int p = 0; p < 4; ++p)
#pragma unroll
        for (int j = 0; j < 8; ++j) acc[p][j] = 0ull;

    for (int k = 0; k < CH; ++k) {
#pragma unroll
        for (int cc = 0; cc < 8; ++cc) {
            int c = k * 8 + cc;
            float4 ua = *(const float4*)&sX[k & 1][cc][lane * 4];
            float4 ub = *(const float4*)&sX[k & 1][cc][128 + lane * 4];
            unsigned long long xp[8] = { pk2(ua.x, ua.x), pk2(ua.y, ua.y),
                                         pk2(ua.z, ua.z), pk2(ua.w, ua.w),
                                         pk2(ub.x, ub.x), pk2(ub.y, ub.y),
                                         pk2(ub.z, ub.z), pk2(ub.w, ub.w) };
            const double2* wp = (const double2*)&sW[c][og];
            double2 w0 = wp[0], w1 = wp[1];
            unsigned long long wq[4] = {
                __double_as_longlong(w0.x), __double_as_longlong(w0.y),
                __double_as_longlong(w1.x), __double_as_longlong(w1.y) };
#pragma unroll
            for (int p = 0; p < 4; ++p)
#pragma unroll
                for (int j = 0; j < 8; ++j)
                    acc[p][j] = f2fma(wq[p], xp[j], acc[p][j]);
        }
        if (k + 1 < CH) {
            float4 va = na, vb = nb;
            if (ACT) { int ch = (k + 1) * 8 + w; float a = sA[ch], d = sD[ch];
                va.x = fmaxf(fmaf(a, va.x, d), 0.f); va.y = fmaxf(fmaf(a, va.y, d), 0.f);
                va.z = fmaxf(fmaf(a, va.z, d), 0.f); va.w = fmaxf(fmaf(a, va.w, d), 0.f);
                vb.x = fmaxf(fmaf(a, vb.x, d), 0.f); vb.y = fmaxf(fmaf(a, vb.y, d), 0.f);
                vb.z = fmaxf(fmaf(a, vb.z, d), 0.f); vb.w = fmaxf(fmaf(a, vb.w, d), 0.f); }
            *(float4*)&sX[(k + 1) & 1][w][lane * 4]       = va;
            *(float4*)&sX[(k + 1) & 1][w][128 + lane * 4] = vb;
            if (k + 2 < CH) {
                na = *(const float4*)(ip + (size_t)((k + 2) * 8 + w) * MPB + lane * 4);
                nb = *(const float4*)(ip + (size_t)((k + 2) * 8 + w) * MPB + 128 + lane * 4);
            }
        }
        __syncthreads();
    }

    float* op = out + (size_t)b * 64 * MPB + mblk * 256;
    int pblk = b * 256 + mblk;
#pragma unroll
    for (int p = 0; p < 4; ++p) {
        float4 a0, a1, b0, b1;
        upk2(acc[p][0], a0.x, a1.x); upk2(acc[p][1], a0.y, a1.y);
        upk2(acc[p][2], a0.z, a1.z); upk2(acc[p][3], a0.w, a1.w);
        upk2(acc[p][4], b0.x, b1.x); upk2(acc[p][5], b0.y, b1.y);
        upk2(acc[p][6], b0.z, b1.z); upk2(acc[p][7], b0.w, b1.w);
        int o0 = og + 2*p, o1 = og + 2*p + 1;
        *(float4*)(op + (size_t)o0 * MPB + lane * 4)       = a0;
        *(float4*)(op + (size_t)o0 * MPB + 128 + lane * 4) = b0;
        *(float4*)(op + (size_t)o1 * MPB + lane * 4)       = a1;
        *(float4*)(op + (size_t)o1 * MPB + 128 + lane * 4) = b1;
        float s0 = (a0.x + a0.y + a0.z + a0.w) + (b0.x + b0.y + b0.z + b0.w);
        float q0 = (a0.x*a0.x + a0.y*a0.y + a0.z*a0.z + a0.w*a0.w)
                 + (b0.x*b0.x + b0.y*b0.y + b0.z*b0.z + b0.w*b0.w);
        float s1 = (a1.x + a1.y + a1.z + a1.w) + (b1.x + b1.y + b1.z + b1.w);
        float q1 = (a1.x*a1.x + a1.y*a1.y + a1.z*a1.z + a1.w*a1.w)
                 + (b1.x*b1.x + b1.y*b1.y + b1.z*b1.z + b1.w*b1.w);
#pragma unroll
        for (int off = 16; off; off >>= 1) {
            s0 += __shfl_xor_sync(0xffffffffu, s0, off);
            q0 += __shfl_xor_sync(0xffffffffu, q0, off);
            s1 += __shfl_xor_sync(0xffffffffu, s1, off);
            q1 += __shfl_xor_sync(0xffffffffu, q1, off);
        }
        if (lane == 0) {
            ps[o0 * NPB + pblk] = s0;  pq[o0 * NPB + pblk] = q0;
            ps[o1 * NPB + pblk] = s1;  pq[o1 * NPB + pblk] = q1;
        }
    }
}

// ---------------- stage-2 stats: NPB partials -> affine coeffs ----------------
__global__ __launch_bounds__(256) void statsfin2_kernel(const float* __restrict__ ps,
                                                        const float* __restrict__ pq,
                                                        const float* __restrict__ gam,
                                                        const float* __restrict__ bet,
                                                        float* __restrict__ aff)
{
    int o = blockIdx.x, tid = threadIdx.x;
    float s = 0.f, q = 0.f;
    for (int i = tid; i < NPB; i += 256) { s += ps[o*NPB + i]; q += pq[o*NPB + i]; }
    __shared__ float rs[256], rq[256];
    rs[tid] = s; rq[tid] = q;
    for (int off = 128; off; off >>= 1) {
        __syncthreads();
        if (tid < off) { rs[tid] += rs[tid + off]; rq[tid] += rq[tid + off]; }
    }
    if (tid == 0) {
        const float invn = 1.f / (float)(NB * MPB);
        float mean = rs[0] * invn;
        float var  = rq[0] * invn - mean * mean;
        float a = gam[o] * rsqrtf(var + 1e-5f);
        aff[o] = a;
        aff[64 + o] = bet[o] - a * mean;
    }
}

// ---------------- residual: x1 = relu(aff2(t2) + relu(aff0(y0))) ----------------
__global__ __launch_bounds__(256) void resid_kernel(const float* __restrict__ y0,
                                                    const float* __restrict__ t2,
                                                    const float* __restrict__ aff0,
                                                    const float* __restrict__ aff2,
                                                    float* __restrict__ x1)
{
    size_t i = (size_t)blockIdx.x * 256 + threadIdx.x;
    int c = (int)((i >> 14) & 63);
    float a0 = aff0[c], d0 = aff0[64+c], a2 = aff2[c], d2 = aff2[64+c];
    float4 y = ((const float4*)y0)[i];
    float4 t = ((const float4*)t2)[i];
    float4 r;
    r.x = fmaxf(fmaf(a2, t.x, d2) + fmaxf(fmaf(a0, y.x, d0), 0.f), 0.f);
    r.y = fmaxf(fmaf(a2, t.y, d2) + fmaxf(fmaf(a0, y.y, d0), 0.f), 0.f);
    r.z = fmaxf(fmaf(a2, t.z, d2) + fmaxf(fmaf(a0, y.z, d0), 0.f), 0.f);
    r.w = fmaxf(fmaf(a2, t.w, d2) + fmaxf(fmaf(a0, y.w, d0), 0.f), 0.f);
    ((float4*)x1)[i] = r;
}

// ---------------- final: feat = max_k relu(aff4(t4) + x1) ----------------
__global__ __launch_bounds__(256) void finalmax_kernel(const float* __restrict__ t4,
                                                       const float* __restrict__ x1,
                                                       const float* __restrict__ aff,
                                                       float* __restrict__ outf)
{
    int g = blockIdx.x * 256 + threadIdx.x;
    int s = g & 2047, o = (g >> 11) & 63, b = g >> 17;
    float a = aff[o], d = aff[64 + o];
    size_t base = (size_t)(b*64 + o) * MPB + s;
    const float* tp = t4 + base;
    const float* xp = x1 + base;
    float m = -1e30f;
#pragma unroll 8
    for (int k = 0; k < 32; ++k)
        m = fmaxf(m, fmaf(a, tp[(size_t)k*2048], d) + xp[(size_t)k*2048]);
    outf[g] = fmaxf(m, 0.f);
}

extern "C" void kernel_launch(void* const* d_in, const int* in_sizes, int n_in,
                              void* d_out, int out_size)
{
    (void)in_sizes; (void)n_in; (void)out_size;
    const float* xyz = (const float*)d_in[0];
    const float* pts = (const float*)d_in[1];
    const float* pw  = (const float*)d_in[2];
    const float* pg  = (const float*)d_in[3];
    const float* pb  = (const float*)d_in[4];
    const float* w1  = (const float*)d_in[5];
    const float* g1  = (const float*)d_in[6];
    const float* b1  = (const float*)d_in[7];
    const float* w2  = (const float*)d_in[8];
    const float* g2  = (const float*)d_in[9];
    const float* b2  = (const float*)d_in[10];

    float *y0, *t1, *t2, *x1, *nx, *ps, *pq, *aff; int* gi;
    cudaGetSymbolAddress((void**)&y0,  g_y0);
    cudaGetSymbolAddress((void**)&t1,  g_t1);
    cudaGetSymbolAddress((void**)&t2,  g_t2);
    cudaGetSymbolAddress((void**)&x1,  g_x1);
    cudaGetSymbolAddress((void**)&nx,  g_nxyz);
    cudaGetSymbolAddress((void**)&gi,  g_idx);
    cudaGetSymbolAddress((void**)&ps,  g_ps);
    cudaGetSymbolAddress((void**)&pq,  g_pq);
    cudaGetSymbolAddress((void**)&aff, g_aff);
    float* out = (float*)d_out;

    cudaFuncSetAttribute(fps_kernel, cudaFuncAttributeMaxDynamicSharedMemorySize,
                         NPTS * (int)sizeof(float4));

    fps_kernel<<<NB * 4, 256, NPTS * sizeof(float4)>>>(xyz, out, nx);
    ball_kernel<<<1024, 256>>>(xyz, nx, gi);
    gather_kernel<<<1024, 256>>>(xyz, pts, gi, nx, t2);

    conv_kernel<32, false><<<1024, 256>>>(t2, pw, nullptr, y0, ps, pq);
    statsfin2_kernel<<<64, 256>>>(ps, pq, pg, pb, aff);

    conv_kernel<64, true><<<1024, 256>>>(y0, w1, aff, t1, ps, pq);
    statsfin2_kernel<<<64, 256>>>(ps, pq, g1, b1, aff + 128);

    conv_kernel<64, true><<<1024, 256>>>(t1, w2, aff + 128, t2, ps, pq);
    statsfin2_kernel<<<64, 256>>>(ps, pq, g2, b2, aff + 256);

    resid_kernel<<<16384, 256>>>(y0, t2, aff, aff + 256, x1);

    conv_kernel<64, false><<<1024, 256>>>(x1, w1 + 4096, nullptr, t1, ps, pq);
    statsfin2_kernel<<<64, 256>>>(ps, pq, g1 + 64, b1 + 64, aff + 384);

    conv_kernel<64, true><<<1024, 256>>>(t1, w2 + 4096, aff + 384, t2, ps, pq);
    statsfin2_kernel<<<64, 256>>>(ps, pq, g2 + 64, b2 + 64, aff + 512);

    finalmax_kernel<<<2048, 256>>>(t2, x1, aff + 512, out + NB*3*NS);
}

// round 13
// speedup vs baseline: 1.7528x; 1.7528x over previous
#include <cuda_runtime.h>
#include <cstdint>

#define NPTS 8192
#define NS   2048
#define NK   32
#define NB   4
#define MPB  65536              /* NK*NS per batch */
#define FSZ  (NB*64*MPB)        /* 16.7M floats per feature buffer */
#define NPB  1024               /* stats partial blocks (4*256) */

__device__ float g_y0[FSZ];
__device__ float g_t1[FSZ];
__device__ float g_t2[FSZ];
__device__ float g_x1[FSZ];
__device__ float g_nxyz[NB*NS*3];
__device__ int   g_idx[NB*NK*NS];
__device__ float g_ps[64*2048];
__device__ float g_pq[64*2048];
__device__ float g_aff[5*128];

static __device__ __forceinline__ unsigned long long pk2(float lo, float hi){
    unsigned long long r; asm("mov.b64 %0,{%1,%2};" : "=l"(r) : "f"(lo), "f"(hi)); return r;
}
static __device__ __forceinline__ void upk2(unsigned long long v, float& lo, float& hi){
    asm("mov.b64 {%0,%1},%2;" : "=f"(lo), "=f"(hi) : "l"(v));
}
static __device__ __forceinline__ void upk2u(unsigned long long v, unsigned& lo, unsigned& hi){
    asm("mov.b64 {%0,%1},%2;" : "=r"(lo), "=r"(hi) : "l"(v));
}
static __device__ __forceinline__ unsigned long long f2fma(unsigned long long a, unsigned long long b, unsigned long long c){
    unsigned long long r; asm("fma.rn.f32x2 %0,%1,%2,%3;" : "=l"(r) : "l"(a), "l"(b), "l"(c)); return r;
}
static __device__ __forceinline__ unsigned long long f2mul(unsigned long long a, unsigned long long b){
    unsigned long long r; asm("mul.rn.f32x2 %0,%1,%2;" : "=l"(r) : "l"(a), "l"(b)); return r;
}
static __device__ __forceinline__ unsigned long long f2add(unsigned long long a, unsigned long long b){
    unsigned long long r; asm("add.rn.f32x2 %0,%1,%2;" : "=l"(r) : "l"(a), "l"(b)); return r;
}
static __device__ __forceinline__ unsigned long long f2sub(unsigned long long a, unsigned long long b){
    unsigned long long r; asm("sub.rn.f32x2 %0,%1,%2;" : "=l"(r) : "l"(a), "l"(b)); return r;
}
static __device__ __forceinline__ unsigned smem_u32(const void* p){
    unsigned a; asm("{ .reg .u64 t; cvta.to.shared.u64 t, %1; cvt.u32.u64 %0, t; }" : "=r"(a) : "l"(p));
    return a;
}
static __device__ __forceinline__ unsigned ctarank(){
    unsigned r; asm("mov.u32 %0, %%cluster_ctarank;" : "=r"(r)); return r;
}
static __device__ __forceinline__ unsigned mapa_u32(unsigned laddr, unsigned r){
    unsigned a; asm("mapa.shared::cluster.u32 %0, %1, %2;" : "=r"(a) : "r"(laddr), "r"(r)); return a;
}
static __device__ __forceinline__ void stc64(unsigned addr, unsigned long long v){
    asm volatile("st.shared::cluster.u64 [%0], %1;" :: "r"(addr), "l"(v) : "memory");
}

// -------- FPS v8: 4-CTA cluster, FENCELESS single-word winner exchange --------
// Each CTA updates min-dists for its 2048-point quarter (exact sub/mul/add
// chain, bit-identical). Exchange: one 64-bit remote store per peer carrying
// (seq16 << 48) | (key32 << 16) | idx13 -- the freshness flag IS the data, so
// no cluster fences. Readers spin on local slots until seq matches, then
// combine with max((key<<13)|(8191-idx)) -> exact first-occurrence argmax.
extern __shared__ float4 spts[];    // 8192 float4 = 128KB (orig order)

__global__ __launch_bounds__(256, 1) __cluster_dims__(4, 1, 1)
void fps_kernel(const float* __restrict__ xyz,
                float* __restrict__ outxyz,
                float* __restrict__ nxyz)
{
    int tid = threadIdx.x, lane = tid & 31, wid = tid >> 5;   // 8 warps
    unsigned rank = ctarank();
    int b = blockIdx.x >> 2;
    const float* X = xyz + (size_t)b * 3 * NPTS;

    __shared__ unsigned swm[32];
    __shared__ unsigned swin[2];
    __shared__ unsigned long long sdata[2][4];   // [parity][src rank]

    if (tid < 8) ((unsigned long long*)sdata)[tid] = 0ull;   // seq=0 != 1..2048
    if (tid < 2) swin[tid] = 0xffffffffu;
    if (tid >= 8 && tid < 32) swm[tid] = 0u;

    // full mirror of all 8192 points (original order)
#pragma unroll 4
    for (int j = 0; j < 32; ++j) {
        int n = tid + j * 256;
        spts[n] = make_float4(X[n], X[NPTS + n], X[2*NPTS + n], 0.f);
    }
    __syncthreads();

    // my quarter: 8 points per thread
    int base = (int)rank * 2048 + tid * 8;
    unsigned long long x2[4], y2[4], z2[4];
    unsigned dist[8];
#pragma unroll
    for (int p = 0; p < 4; ++p) {
        float4 A = spts[base + 2*p];
        float4 B = spts[base + 2*p + 1];
        x2[p] = pk2(A.x, B.x); y2[p] = pk2(A.y, B.y); z2[p] = pk2(A.z, B.z);
        dist[2*p] = __float_as_uint(1e10f); dist[2*p+1] = __float_as_uint(1e10f);
    }

    unsigned data_base = smem_u32(&sdata[0][0]);
    unsigned my_doff[2];
    my_doff[0] = data_base + rank * 8u;
    my_doff[1] = data_base + (4u + rank) * 8u;

    // all CTAs' smem init visible before any remote write
    asm volatile("barrier.cluster.arrive.aligned;" ::: "memory");
    asm volatile("barrier.cluster.wait.aligned;" ::: "memory");

    float cx = X[0], cy = X[NPTS], cz = X[2*NPTS];

    for (int it = 0; it < NS; ++it) {
        if (rank == 0 && tid == 0) {
            outxyz[(b*3 + 0)*NS + it] = cx;
            outxyz[(b*3 + 1)*NS + it] = cy;
            outxyz[(b*3 + 2)*NS + it] = cz;
            nxyz[((size_t)b*NS + it)*3 + 0] = cx;
            nxyz[((size_t)b*NS + it)*3 + 1] = cy;
            nxyz[((size_t)b*NS + it)*3 + 2] = cz;
        }
        unsigned long long cx2 = pk2(cx, cx);
        unsigned long long cy2 = pk2(cy, cy);
        unsigned long long cz2 = pk2(cz, cz);

#pragma unroll
        for (int p = 0; p < 4; ++p) {
            unsigned long long dx = f2sub(x2[p], cx2);
            unsigned long long dy = f2sub(y2[p], cy2);
            unsigned long long dz = f2sub(z2[p], cz2);
            // (dx*dx + dy*dy) + dz*dz -- lane-wise identical to scalar rounding
            unsigned long long s = f2add(f2add(f2mul(dx, dx), f2mul(dy, dy)), f2mul(dz, dz));
            unsigned slo, shi; upk2u(s, slo, shi);
            dist[2*p]   = min(dist[2*p],   slo);
            dist[2*p+1] = min(dist[2*p+1], shi);
        }
        unsigned key = 0u;
#pragma unroll
        for (int j = 0; j < 8; ++j) key = max(key, dist[j]);

        unsigned kmax = __reduce_max_sync(0xffffffffu, key);
        if (lane == 0) swm[wid] = kmax;
        __syncthreads();                               // b1
        unsigned g = __reduce_max_sync(0xffffffffu, swm[lane]);
        if (tid == 0) swin[(it + 1) & 1] = 0xffffffffu;
        if (key == g) {
            unsigned li = 0xffffffffu;
#pragma unroll
            for (int p = 3; p >= 0; --p) {             // lo overwrites hi
                if (dist[2*p+1] == g) li = (unsigned)(base + 2*p + 1);
                if (dist[2*p]   == g) li = (unsigned)(base + 2*p);
            }
            atomicMin(&swin[it & 1], li);              // CTA-local min orig idx
        }
        __syncthreads();                               // b2

        int par = it & 1;
        unsigned tgt = (unsigned)((it + 1) & 0xFFFF);
        if (tid == 0) {
            unsigned long long pack = ((unsigned long long)tgt << 48)
                                    | ((unsigned long long)g << 16)
                                    | (unsigned long long)(swin[par] & 0x1FFFu);
            unsigned doff = my_doff[par];
#pragma unroll
            for (unsigned r = 0; r < 4; ++r) stc64(mapa_u32(doff, r), pack);
        }
        // spin on local slots: seq field == it+1 from all 4 sources
        volatile unsigned long long* vd = (volatile unsigned long long*)&sdata[par][0];
        unsigned long long w0, w1, w2, w3;
        for (;;) {
            w0 = vd[0]; w1 = vd[1]; w2 = vd[2]; w3 = vd[3];
            if ((unsigned)(w0 >> 48) == tgt && (unsigned)(w1 >> 48) == tgt &&
                (unsigned)(w2 >> 48) == tgt && (unsigned)(w3 >> 48) == tgt) break;
        }
        // combine: max over (key<<13) | (8191 - idx) -> max key, min idx
        unsigned long long c0 = (((w0 >> 16) & 0xFFFFFFFFull) << 13) | (8191ull - (w0 & 0x1FFFull));
        unsigned long long c1 = (((w1 >> 16) & 0xFFFFFFFFull) << 13) | (8191ull - (w1 & 0x1FFFull));
        unsigned long long c2 = (((w2 >> 16) & 0xFFFFFFFFull) << 13) | (8191ull - (w2 & 0x1FFFull));
        unsigned long long c3 = (((w3 >> 16) & 0xFFFFFFFFull) << 13) | (8191ull - (w3 & 0x1FFFull));
        unsigned long long win = max(max(c0, c1), max(c2, c3));
        unsigned widx = 8191u - (unsigned)(win & 0x1FFFull);
        float4 cc = spts[widx];
        cx = cc.x; cy = cc.y; cz = cc.z;
    }
    // keep CTAs resident until all have finished the protocol
    asm volatile("barrier.cluster.arrive.aligned;" ::: "memory");
    asm volatile("barrier.cluster.wait.aligned;" ::: "memory");
}

// ---------------- ball query: one warp per center ----------------
__global__ __launch_bounds__(256) void ball_kernel(const float* __restrict__ xyz,
                                                   const float* __restrict__ nxyz,
                                                   int* __restrict__ gidx)
{
    __shared__ int sbuf[8][32];
    int w = threadIdx.x >> 5, lane = threadIdx.x & 31;
    int gid = blockIdx.x * 8 + w;
    int b = gid >> 11, s = gid & 2047;
    const float* X = xyz + (size_t)b * 3 * NPTS;

    float cx = nxyz[gid*3], cy = nxyz[gid*3 + 1], cz = nxyz[gid*3 + 2];
    float cc = __fadd_rn(__fadd_rn(__fmul_rn(cx,cx), __fmul_rn(cy,cy)), __fmul_rn(cz,cz));
    const float R2 = (float)(0.1 * 0.1);

    int cnt = 0;
    for (int base = 0; base < NPTS; base += 32) {
        int n = base + lane;
        float px = X[n], py = X[NPTS + n], pz = X[2*NPTS + n];
        float pp  = __fadd_rn(__fadd_rn(__fmul_rn(px,px), __fmul_rn(py,py)), __fmul_rn(pz,pz));
        float dot = __fadd_rn(__fadd_rn(__fmul_rn(cx,px), __fmul_rn(cy,py)), __fmul_rn(cz,pz));
        float sqr = __fadd_rn(__fadd_rn(cc, pp), -__fmul_rn(2.f, dot));
        bool hit = (sqr <= R2);
        unsigned m = __ballot_sync(0xffffffffu, hit);
        if (m) {
            int rank = cnt + __popc(m & ((1u << lane) - 1u));
            if (hit && rank < 32) sbuf[w][rank] = n;
            cnt += __popc(m);
            if (cnt >= 32) break;
        }
    }
    __syncwarp();
    int first = sbuf[w][0];
    int my = (lane < cnt) ? sbuf[w][lane] : first;
    gidx[((size_t)(b*32 + lane))*2048 + s] = my;
}

// ---------------- gather + center-subtract + concat ----------------
__global__ __launch_bounds__(256) void gather_kernel(const float* __restrict__ xyz,
                                                     const float* __restrict__ pts,
                                                     const int* __restrict__ gidx,
                                                     const float* __restrict__ nxyz,
                                                     float* __restrict__ xin)
{
    int g = blockIdx.x * 256 + threadIdx.x;
    int s = g & 2047, k = (g >> 11) & 31, b = g >> 16;
    int id = gidx[((size_t)(b*32 + k))*2048 + s];
    const float* X = xyz + (size_t)b * 3 * NPTS;
    const float* P = pts + (size_t)b * 29 * NPTS;
    size_t ob = (size_t)b * 32 * MPB + (size_t)k * 2048 + s;
#pragma unroll
    for (int c = 0; c < 3; ++c)
        xin[ob + (size_t)c * MPB] = X[c*NPTS + id] - nxyz[((size_t)(b*2048 + s))*3 + c];
#pragma unroll
    for (int c = 0; c < 29; ++c)
        xin[ob + (size_t)(3 + c) * MPB] = P[c*NPTS + id];
}

// ---------------- conv v3: 256 pts/block, 8 pts/thread, fused stats ----------------
template<int CIN, bool ACT>
__global__ __launch_bounds__(256) void conv_kernel(const float* __restrict__ in,
                                                   const float* __restrict__ W,
                                                   const float* __restrict__ aff,
                                                   float* __restrict__ out,
                                                   float* __restrict__ ps,
                                                   float* __restrict__ pq)
{
    constexpr int CH = CIN / 8;
    __shared__ float sW[CIN][64];
    __shared__ float sX[2][8][256];
    __shared__ float sA[64], sD[64];
    int tid = threadIdx.x, lane = tid & 31, w = tid >> 5;
    int b = blockIdx.x >> 8, mblk = blockIdx.x & 255;
    const float* ip = in + (size_t)b * CIN * MPB + mblk * 256;

    for (int i = tid; i < CIN * 64; i += 256)
        sW[i >> 6][i & 63] = W[(i & 63) * CIN + (i >> 6)];
    if (ACT) for (int i = tid; i < CIN; i += 256) { sA[i] = aff[i]; sD[i] = aff[64 + i]; }

    float4 xa = *(const float4*)(ip + (size_t)w * MPB + lane * 4);
    float4 xb = *(const float4*)(ip + (size_t)w * MPB + 128 + lane * 4);
    float4 na, nb;
    if (CH > 1) {
        na = *(const float4*)(ip + (size_t)(8 + w) * MPB + lane * 4);
        nb = *(const float4*)(ip + (size_t)(8 + w) * MPB + 128 + lane * 4);
    }
    __syncthreads();
    {
        float4 va = xa, vb = xb;
        if (ACT) { float a = sA[w], d = sD[w];
            va.x = fmaxf(fmaf(a, va.x, d), 0.f); va.y = fmaxf(fmaf(a, va.y, d), 0.f);
            va.z = fmaxf(fmaf(a, va.z, d), 0.f); va.w = fmaxf(fmaf(a, va.w, d), 0.f);
            vb.x = fmaxf(fmaf(a, vb.x, d), 0.f); vb.y = fmaxf(fmaf(a, vb.y, d), 0.f);
            vb.z = fmaxf(fmaf(a, vb.z, d), 0.f); vb.w = fmaxf(fmaf(a, vb.w, d), 0.f); }
        *(float4*)&sX[0][w][lane * 4]       = va;
        *(float4*)&sX[0][w][128 + lane * 4] = vb;
    }
    __syncthreads();

    int og = w * 8;
    unsigned long long acc[4][8];
#pragma unroll
    for (int p = 0; p < 4; ++p)
#pragma unroll
        for (int j = 0; j < 8; ++j) acc[p][j] = 0ull;

    for (int k = 0; k < CH; ++k) {
#pragma unroll
        for (int cc = 0; cc < 8; ++cc) {
            int c = k * 8 + cc;
            float4 ua = *(const float4*)&sX[k & 1][cc][lane * 4];
            float4 ub = *(const float4*)&sX[k & 1][cc][128 + lane * 4];
            unsigned long long xp[8] = { pk2(ua.x, ua.x), pk2(ua.y, ua.y),
                                         pk2(ua.z, ua.z), pk2(ua.w, ua.w),
                                         pk2(ub.x, ub.x), pk2(ub.y, ub.y),
                                         pk2(ub.z, ub.z), pk2(ub.w, ub.w) };
            const double2* wp = (const double2*)&sW[c][og];
            double2 w0 = wp[0], w1 = wp[1];
            unsigned long long wq[4] = {
                __double_as_longlong(w0.x), __double_as_longlong(w0.y),
                __double_as_longlong(w1.x), __double_as_longlong(w1.y) };
#pragma unroll
            for (int p = 0; p < 4; ++p)
#pragma unroll
                for (int j = 0; j < 8; ++j)
                    acc[p][j] = f2fma(wq[p], xp[j], acc[p][j]);
        }
        if (k + 1 < CH) {
            float4 va = na, vb = nb;
            if (ACT) { int ch = (k + 1) * 8 + w; float a = sA[ch], d = sD[ch];
                va.x = fmaxf(fmaf(a, va.x, d), 0.f); va.y = fmaxf(fmaf(a, va.y, d), 0.f);
                va.z = fmaxf(fmaf(a, va.z, d), 0.f); va.w = fmaxf(fmaf(a, va.w, d), 0.f);
                vb.x = fmaxf(fmaf(a, vb.x, d), 0.f); vb.y = fmaxf(fmaf(a, vb.y, d), 0.f);
                vb.z = fmaxf(fmaf(a, vb.z, d), 0.f); vb.w = fmaxf(fmaf(a, vb.w, d), 0.f); }
            *(float4*)&sX[(k + 1) & 1][w][lane * 4]       = va;
            *(float4*)&sX[(k + 1) & 1][w][128 + lane * 4] = vb;
            if (k + 2 < CH) {
                na = *(const float4*)(ip + (size_t)((k + 2) * 8 + w) * MPB + lane * 4);
                nb = *(const float4*)(ip + (size_t)((k + 2) * 8 + w) * MPB + 128 + lane * 4);
            }
        }
        __syncthreads();
    }

    float* op = out + (size_t)b * 64 * MPB + mblk * 256;
    int pblk = b * 256 + mblk;
#pragma unroll
    for (int p = 0; p < 4; ++p) {
        float4 a0, a1, b0, b1;
        upk2(acc[p][0], a0.x, a1.x); upk2(acc[p][1], a0.y, a1.y);
        upk2(acc[p][2], a0.z, a1.z); upk2(acc[p][3], a0.w, a1.w);
        upk2(acc[p][4], b0.x, b1.x); upk2(acc[p][5], b0.y, b1.y);
        upk2(acc[p][6], b0.z, b1.z); upk2(acc[p][7], b0.w, b1.w);
        int o0 = og + 2*p, o1 = og + 2*p + 1;
        *(float4*)(op + (size_t)o0 * MPB + lane * 4)       = a0;
        *(float4*)(op + (size_t)o0 * MPB + 128 + lane * 4) = b0;
        *(float4*)(op + (size_t)o1 * MPB + lane * 4)       = a1;
        *(float4*)(op + (size_t)o1 * MPB + 128 + lane * 4) = b1;
        float s0 = (a0.x + a0.y + a0.z + a0.w) + (b0.x + b0.y + b0.z + b0.w);
        float q0 = (a0.x*a0.x + a0.y*a0.y + a0.z*a0.z + a0.w*a0.w)
                 + (b0.x*b0.x + b0.y*b0.y + b0.z*b0.z + b0.w*b0.w);
        float s1 = (a1.x + a1.y + a1.z + a1.w) + (b1.x + b1.y + b1.z + b1.w);
        float q1 = (a1.x*a1.x + a1.y*a1.y + a1.z*a1.z + a1.w*a1.w)
                 + (b1.x*b1.x + b1.y*b1.y + b1.z*b1.z + b1.w*b1.w);
#pragma unroll
        for (int off = 16; off; off >>= 1) {
            s0 += __shfl_xor_sync(0xffffffffu, s0, off);
            q0 += __shfl_xor_sync(0xffffffffu, q0, off);
            s1 += __shfl_xor_sync(0xffffffffu, s1, off);
            q1 += __shfl_xor_sync(0xffffffffu, q1, off);
        }
        if (lane == 0) {
            ps[o0 * NPB + pblk] = s0;  pq[o0 * NPB + pblk] = q0;
            ps[o1 * NPB + pblk] = s1;  pq[o1 * NPB + pblk] = q1;
        }
    }
}

// ---------------- stage-2 stats: NPB partials -> affine coeffs ----------------
__global__ __launch_bounds__(256) void statsfin2_kernel(const float* __restrict__ ps,
                                                        const float* __restrict__ pq,
                                                        const float* __restrict__ gam,
                                                        const float* __restrict__ bet,
                                                        float* __restrict__ aff)
{
    int o = blockIdx.x, tid = threadIdx.x;
    float s = 0.f, q = 0.f;
    for (int i = tid; i < NPB; i += 256) { s += ps[o*NPB + i]; q += pq[o*NPB + i]; }
    __shared__ float rs[256], rq[256];
    rs[tid] = s; rq[tid] = q;
    for (int off = 128; off; off >>= 1) {
        __syncthreads();
        if (tid < off) { rs[tid] += rs[tid + off]; rq[tid] += rq[tid + off]; }
    }
    if (tid == 0) {
        const float invn = 1.f / (float)(NB * MPB);
        float mean = rs[0] * invn;
        float var  = rq[0] * invn - mean * mean;
        float a = gam[o] * rsqrtf(var + 1e-5f);
        aff[o] = a;
        aff[64 + o] = bet[o] - a * mean;
    }
}

// ---------------- residual: x1 = relu(aff2(t2) + relu(aff0(y0))) ----------------
__global__ __launch_bounds__(256) void resid_kernel(const float* __restrict__ y0,
                                                    const float* __restrict__ t2,
                                                    const float* __restrict__ aff0,
                                                    const float* __restrict__ aff2,
                                                    float* __restrict__ x1)
{
    size_t i = (size_t)blockIdx.x * 256 + threadIdx.x;
    int c = (int)((i >> 14) & 63);
    float a0 = aff0[c], d0 = aff0[64+c], a2 = aff2[c], d2 = aff2[64+c];
    float4 y = ((const float4*)y0)[i];
    float4 t = ((const float4*)t2)[i];
    float4 r;
    r.x = fmaxf(fmaf(a2, t.x, d2) + fmaxf(fmaf(a0, y.x, d0), 0.f), 0.f);
    r.y = fmaxf(fmaf(a2, t.y, d2) + fmaxf(fmaf(a0, y.y, d0), 0.f), 0.f);
    r.z = fmaxf(fmaf(a2, t.z, d2) + fmaxf(fmaf(a0, y.z, d0), 0.f), 0.f);
    r.w = fmaxf(fmaf(a2, t.w, d2) + fmaxf(fmaf(a0, y.w, d0), 0.f), 0.f);
    ((float4*)x1)[i] = r;
}

// ---------------- final: feat = max_k relu(aff4(t4) + x1) ----------------
__global__ __launch_bounds__(256) void finalmax_kernel(const float* __restrict__ t4,
                                                       const float* __restrict__ x1,
                                                       const float* __restrict__ aff,
                                                       float* __restrict__ outf)
{
    int g = blockIdx.x * 256 + threadIdx.x;
    int s = g & 2047, o = (g >> 11) & 63, b = g >> 17;
    float a = aff[o], d = aff[64 + o];
    size_t base = (size_t)(b*64 + o) * MPB + s;
    const float* tp = t4 + base;
    const float* xp = x1 + base;
    float m = -1e30f;
#pragma unroll 8
    for (int k = 0; k < 32; ++k)
        m = fmaxf(m, fmaf(a, tp[(size_t)k*2048], d) + xp[(size_t)k*2048]);
    outf[g] = fmaxf(m, 0.f);
}

extern "C" void kernel_launch(void* const* d_in, const int* in_sizes, int n_in,
                              void* d_out, int out_size)
{
    (void)in_sizes; (void)n_in; (void)out_size;
    const float* xyz = (const float*)d_in[0];
    const float* pts = (const float*)d_in[1];
    const float* pw  = (const float*)d_in[2];
    const float* pg  = (const float*)d_in[3];
    const float* pb  = (const float*)d_in[4];
    const float* w1  = (const float*)d_in[5];
    const float* g1  = (const float*)d_in[6];
    const float* b1  = (const float*)d_in[7];
    const float* w2  = (const float*)d_in[8];
    const float* g2  = (const float*)d_in[9];
    const float* b2  = (const float*)d_in[10];

    float *y0, *t1, *t2, *x1, *nx, *ps, *pq, *aff; int* gi;
    cudaGetSymbolAddress((void**)&y0,  g_y0);
    cudaGetSymbolAddress((void**)&t1,  g_t1);
    cudaGetSymbolAddress((void**)&t2,  g_t2);
    cudaGetSymbolAddress((void**)&x1,  g_x1);
    cudaGetSymbolAddress((void**)&nx,  g_nxyz);
    cudaGetSymbolAddress((void**)&gi,  g_idx);
    cudaGetSymbolAddress((void**)&ps,  g_ps);
    cudaGetSymbolAddress((void**)&pq,  g_pq);
    cudaGetSymbolAddress((void**)&aff, g_aff);
    float* out = (float*)d_out;

    cudaFuncSetAttribute(fps_kernel, cudaFuncAttributeMaxDynamicSharedMemorySize,
                         NPTS * (int)sizeof(float4));

    fps_kernel<<<NB * 4, 256, NPTS * sizeof(float4)>>>(xyz, out, nx);
    ball_kernel<<<1024, 256>>>(xyz, nx, gi);
    gather_kernel<<<1024, 256>>>(xyz, pts, gi, nx, t2);

    conv_kernel<32, false><<<1024, 256>>>(t2, pw, nullptr, y0, ps, pq);
    statsfin2_kernel<<<64, 256>>>(ps, pq, pg, pb, aff);

    conv_kernel<64, true><<<1024, 256>>>(y0, w1, aff, t1, ps, pq);
    statsfin2_kernel<<<64, 256>>>(ps, pq, g1, b1, aff + 128);

    conv_kernel<64, true><<<1024, 256>>>(t1, w2, aff + 128, t2, ps, pq);
    statsfin2_kernel<<<64, 256>>>(ps, pq, g2, b2, aff + 256);

    resid_kernel<<<16384, 256>>>(y0, t2, aff, aff + 256, x1);

    conv_kernel<64, false><<<1024, 256>>>(x1, w1 + 4096, nullptr, t1, ps, pq);
    statsfin2_kernel<<<64, 256>>>(ps, pq, g1 + 64, b1 + 64, aff + 384);

    conv_kernel<64, true><<<1024, 256>>>(t1, w2 + 4096, aff + 384, t2, ps, pq);
    statsfin2_kernel<<<64, 256>>>(ps, pq, g2 + 64, b2 + 64, aff + 512);

    finalmax_kernel<<<2048, 256>>>(t2, x1, aff + 512, out + NB*3*NS);
}

// round 14
// speedup vs baseline: 1.8284x; 1.0432x over previous
#include <cuda_runtime.h>
#include <cstdint>

#define NPTS 8192
#define NS   2048
#define NK   32
#define NB   4
#define MPB  65536              /* NK*NS per batch */
#define FSZ  (NB*64*MPB)        /* 16.7M floats per feature buffer */
#define NPB  1024               /* stats partial blocks (4*256) */

__device__ float g_y0[FSZ];
__device__ float g_t1[FSZ];
__device__ float g_t2[FSZ];
__device__ float g_x1[FSZ];
__device__ float g_nxyz[NB*NS*3];
__device__ int   g_idx[NB*NK*NS];
__device__ float g_ps[64*2048];
__device__ float g_pq[64*2048];
__device__ float g_aff[5*128];

static __device__ __forceinline__ unsigned long long pk2(float lo, float hi){
    unsigned long long r; asm("mov.b64 %0,{%1,%2};" : "=l"(r) : "f"(lo), "f"(hi)); return r;
}
static __device__ __forceinline__ void upk2(unsigned long long v, float& lo, float& hi){
    asm("mov.b64 {%0,%1},%2;" : "=f"(lo), "=f"(hi) : "l"(v));
}
static __device__ __forceinline__ void upk2u(unsigned long long v, unsigned& lo, unsigned& hi){
    asm("mov.b64 {%0,%1},%2;" : "=r"(lo), "=r"(hi) : "l"(v));
}
static __device__ __forceinline__ unsigned long long f2fma(unsigned long long a, unsigned long long b, unsigned long long c){
    unsigned long long r; asm("fma.rn.f32x2 %0,%1,%2,%3;" : "=l"(r) : "l"(a), "l"(b), "l"(c)); return r;
}
static __device__ __forceinline__ unsigned long long f2mul(unsigned long long a, unsigned long long b){
    unsigned long long r; asm("mul.rn.f32x2 %0,%1,%2;" : "=l"(r) : "l"(a), "l"(b)); return r;
}
static __device__ __forceinline__ unsigned long long f2add(unsigned long long a, unsigned long long b){
    unsigned long long r; asm("add.rn.f32x2 %0,%1,%2;" : "=l"(r) : "l"(a), "l"(b)); return r;
}
static __device__ __forceinline__ unsigned long long f2sub(unsigned long long a, unsigned long long b){
    unsigned long long r; asm("sub.rn.f32x2 %0,%1,%2;" : "=l"(r) : "l"(a), "l"(b)); return r;
}
static __device__ __forceinline__ unsigned smem_u32(const void* p){
    unsigned a; asm("{ .reg .u64 t; cvta.to.shared.u64 t, %1; cvt.u32.u64 %0, t; }" : "=r"(a) : "l"(p));
    return a;
}
static __device__ __forceinline__ unsigned ctarank(){
    unsigned r; asm("mov.u32 %0, %%cluster_ctarank;" : "=r"(r)); return r;
}
static __device__ __forceinline__ unsigned mapa_u32(unsigned laddr, unsigned r){
    unsigned a; asm("mapa.shared::cluster.u32 %0, %1, %2;" : "=r"(a) : "r"(laddr), "r"(r)); return a;
}
static __device__ __forceinline__ void stc64(unsigned addr, unsigned long long v){
    asm volatile("st.shared::cluster.u64 [%0], %1;" :: "r"(addr), "l"(v) : "memory");
}

// -------- FPS v9: 4-CTA cluster, per-WARP fenceless exchange, 0 barriers/iter ----
// Each of 32 warps (4 CTAs x 8) publishes its own packed winner
// (seq16<<48 | key32<<16 | (8191-idx)) to all 4 CTAs; every warp polls its 32
// local slots (lane i polls slot i) and 64-bit shfl-max-reduces. Direct max on
// packs = max key then min idx -> exact first-occurrence argmax. 2-deep parity
// slots make overwrite provably impossible (a warp reaches it+2 only after all
// warps stored it+1, which happens only after each finished reading it).
extern __shared__ float4 spts[];    // 8192 float4 = 128KB (orig order)

__global__ __launch_bounds__(256, 1) __cluster_dims__(4, 1, 1)
void fps_kernel(const float* __restrict__ xyz,
                float* __restrict__ outxyz,
                float* __restrict__ nxyz)
{
    int tid = threadIdx.x, lane = tid & 31, wid = tid >> 5;   // 8 warps
    unsigned rank = ctarank();
    int b = blockIdx.x >> 2;
    const float* X = xyz + (size_t)b * 3 * NPTS;

    __shared__ unsigned long long sdata[2][32];   // [parity][global warp 0..31]

    if (tid < 64) ((unsigned long long*)sdata)[tid] = 0ull;   // seq=0 != 1..2048

    // full mirror of all 8192 points (original order)
#pragma unroll 4
    for (int j = 0; j < 32; ++j) {
        int n = tid + j * 256;
        spts[n] = make_float4(X[n], X[NPTS + n], X[2*NPTS + n], 0.f);
    }
    __syncthreads();

    // my quarter: 8 points per thread
    int base = (int)rank * 2048 + tid * 8;
    unsigned long long x2[4], y2[4], z2[4];
    unsigned dist[8];
#pragma unroll
    for (int p = 0; p < 4; ++p) {
        float4 A = spts[base + 2*p];
        float4 B = spts[base + 2*p + 1];
        x2[p] = pk2(A.x, B.x); y2[p] = pk2(A.y, B.y); z2[p] = pk2(A.z, B.z);
        dist[2*p] = __float_as_uint(1e10f); dist[2*p+1] = __float_as_uint(1e10f);
    }

    unsigned slot_base = smem_u32(&sdata[0][0]);
    unsigned gw = rank * 8u + (unsigned)wid;       // global warp id
    unsigned my_off[2] = { slot_base + gw * 8u, slot_base + (32u + gw) * 8u };

    // all CTAs' smem init visible before any remote write
    asm volatile("barrier.cluster.arrive.aligned;" ::: "memory");
    asm volatile("barrier.cluster.wait.aligned;" ::: "memory");

    float cx = X[0], cy = X[NPTS], cz = X[2*NPTS];

    for (int it = 0; it < NS; ++it) {
        if (rank == 0 && tid == 0) {
            outxyz[(b*3 + 0)*NS + it] = cx;
            outxyz[(b*3 + 1)*NS + it] = cy;
            outxyz[(b*3 + 2)*NS + it] = cz;
            nxyz[((size_t)b*NS + it)*3 + 0] = cx;
            nxyz[((size_t)b*NS + it)*3 + 1] = cy;
            nxyz[((size_t)b*NS + it)*3 + 2] = cz;
        }
        unsigned long long cx2 = pk2(cx, cx);
        unsigned long long cy2 = pk2(cy, cy);
        unsigned long long cz2 = pk2(cz, cz);

#pragma unroll
        for (int p = 0; p < 4; ++p) {
            unsigned long long dx = f2sub(x2[p], cx2);
            unsigned long long dy = f2sub(y2[p], cy2);
            unsigned long long dz = f2sub(z2[p], cz2);
            // (dx*dx + dy*dy) + dz*dz -- lane-wise identical to scalar rounding
            unsigned long long s = f2add(f2add(f2mul(dx, dx), f2mul(dy, dy)), f2mul(dz, dz));
            unsigned slo, shi; upk2u(s, slo, shi);
            dist[2*p]   = min(dist[2*p],   slo);
            dist[2*p+1] = min(dist[2*p+1], shi);
        }
        unsigned key = 0u;
#pragma unroll
        for (int j = 0; j < 8; ++j) key = max(key, dist[j]);

        unsigned wmax = __reduce_max_sync(0xffffffffu, key);
        unsigned li = 0xffffffffu;
#pragma unroll
        for (int p = 3; p >= 0; --p) {                 // lo overwrites hi -> min in thread
            if (dist[2*p+1] == wmax) li = (unsigned)(base + 2*p + 1);
            if (dist[2*p]   == wmax) li = (unsigned)(base + 2*p);
        }
        unsigned wmin = __reduce_min_sync(0xffffffffu, li);   // warp min orig idx

        int par = it & 1;
        unsigned tgt = (unsigned)((it + 1) & 0xFFFF);
        if (lane == 0) {
            unsigned long long pack = ((unsigned long long)tgt << 48)
                                    | ((unsigned long long)wmax << 16)
                                    | (unsigned long long)(8191u - (wmin & 0x1FFFu));
            unsigned doff = my_off[par];
#pragma unroll
            for (unsigned r = 0; r < 4; ++r) stc64(mapa_u32(doff, r), pack);
        }
        // poll: lane i watches slot i until all 32 carry seq == it+1
        volatile unsigned long long* vd = (volatile unsigned long long*)&sdata[par][0];
        unsigned long long v;
        do { v = vd[lane]; } while (!__all_sync(0xffffffffu, (unsigned)(v >> 48) == tgt));
        // 64-bit max-reduce across lanes: max key, then min idx (complemented)
        unsigned long long m = v;
#pragma unroll
        for (int off = 16; off; off >>= 1) {
            unsigned long long o = __shfl_xor_sync(0xffffffffu, m, off);
            m = max(m, o);
        }
        unsigned widx = 8191u - (unsigned)(m & 0x1FFFull);
        float4 cc = spts[widx];
        cx = cc.x; cy = cc.y; cz = cc.z;
    }
    // keep CTAs resident until all have finished the protocol
    asm volatile("barrier.cluster.arrive.aligned;" ::: "memory");
    asm volatile("barrier.cluster.wait.aligned;" ::: "memory");
}

// ---------------- ball query: one warp per center ----------------
__global__ __launch_bounds__(256) void ball_kernel(const float* __restrict__ xyz,
                                                   const float* __restrict__ nxyz,
                                                   int* __restrict__ gidx)
{
    __shared__ int sbuf[8][32];
    int w = threadIdx.x >> 5, lane = threadIdx.x & 31;
    int gid = blockIdx.x * 8 + w;
    int b = gid >> 11, s = gid & 2047;
    const float* X = xyz + (size_t)b * 3 * NPTS;

    float cx = nxyz[gid*3], cy = nxyz[gid*3 + 1], cz = nxyz[gid*3 + 2];
    float cc = __fadd_rn(__fadd_rn(__fmul_rn(cx,cx), __fmul_rn(cy,cy)), __fmul_rn(cz,cz));
    const float R2 = (float)(0.1 * 0.1);

    int cnt = 0;
    for (int base = 0; base < NPTS; base += 32) {
        int n = base + lane;
        float px = X[n], py = X[NPTS + n], pz = X[2*NPTS + n];
        float pp  = __fadd_rn(__fadd_rn(__fmul_rn(px,px), __fmul_rn(py,py)), __fmul_rn(pz,pz));
        float dot = __fadd_rn(__fadd_rn(__fmul_rn(cx,px), __fmul_rn(cy,py)), __fmul_rn(cz,pz));
        float sqr = __fadd_rn(__fadd_rn(cc, pp), -__fmul_rn(2.f, dot));
        bool hit = (sqr <= R2);
        unsigned m = __ballot_sync(0xffffffffu, hit);
        if (m) {
            int rank = cnt + __popc(m & ((1u << lane) - 1u));
            if (hit && rank < 32) sbuf[w][rank] = n;
            cnt += __popc(m);
            if (cnt >= 32) break;
        }
    }
    __syncwarp();
    int first = sbuf[w][0];
    int my = (lane < cnt) ? sbuf[w][lane] : first;
    gidx[((size_t)(b*32 + lane))*2048 + s] = my;
}

// ---------------- gather + center-subtract + concat ----------------
__global__ __launch_bounds__(256) void gather_kernel(const float* __restrict__ xyz,
                                                     const float* __restrict__ pts,
                                                     const int* __restrict__ gidx,
                                                     const float* __restrict__ nxyz,
                                                     float* __restrict__ xin)
{
    int g = blockIdx.x * 256 + threadIdx.x;
    int s = g & 2047, k = (g >> 11) & 31, b = g >> 16;
    int id = gidx[((size_t)(b*32 + k))*2048 + s];
    const float* X = xyz + (size_t)b * 3 * NPTS;
    const float* P = pts + (size_t)b * 29 * NPTS;
    size_t ob = (size_t)b * 32 * MPB + (size_t)k * 2048 + s;
#pragma unroll
    for (int c = 0; c < 3; ++c)
        xin[ob + (size_t)c * MPB] = X[c*NPTS + id] - nxyz[((size_t)(b*2048 + s))*3 + c];
#pragma unroll
    for (int c = 0; c < 29; ++c)
        xin[ob + (size_t)(3 + c) * MPB] = P[c*NPTS + id];
}

// ---------------- conv v3: 256 pts/block, 8 pts/thread, fused stats ----------------
template<int CIN, bool ACT>
__global__ __launch_bounds__(256) void conv_kernel(const float* __restrict__ in,
                                                   const float* __restrict__ W,
                                                   const float* __restrict__ aff,
                                                   float* __restrict__ out,
                                                   float* __restrict__ ps,
                                                   float* __restrict__ pq)
{
    constexpr int CH = CIN / 8;
    __shared__ float sW[CIN][64];
    __shared__ float sX[2][8][256];
    __shared__ float sA[64], sD[64];
    int tid = threadIdx.x, lane = tid & 31, w = tid >> 5;
    int b = blockIdx.x >> 8, mblk = blockIdx.x & 255;
    const float* ip = in + (size_t)b * CIN * MPB + mblk * 256;

    for (int i = tid; i < CIN * 64; i += 256)
        sW[i >> 6][i & 63] = W[(i & 63) * CIN + (i >> 6)];
    if (ACT) for (int i = tid; i < CIN; i += 256) { sA[i] = aff[i]; sD[i] = aff[64 + i]; }

    float4 xa = *(const float4*)(ip + (size_t)w * MPB + lane * 4);
    float4 xb = *(const float4*)(ip + (size_t)w * MPB + 128 + lane * 4);
    float4 na, nb;
    if (CH > 1) {
        na = *(const float4*)(ip + (size_t)(8 + w) * MPB + lane * 4);
        nb = *(const float4*)(ip + (size_t)(8 + w) * MPB + 128 + lane * 4);
    }
    __syncthreads();
    {
        float4 va = xa, vb = xb;
        if (ACT) { float a = sA[w], d = sD[w];
            va.x = fmaxf(fmaf(a, va.x, d), 0.f); va.y = fmaxf(fmaf(a, va.y, d), 0.f);
            va.z = fmaxf(fmaf(a, va.z, d), 0.f); va.w = fmaxf(fmaf(a, va.w, d), 0.f);
            vb.x = fmaxf(fmaf(a, vb.x, d), 0.f); vb.y = fmaxf(fmaf(a, vb.y, d), 0.f);
            vb.z = fmaxf(fmaf(a, vb.z, d), 0.f); vb.w = fmaxf(fmaf(a, vb.w, d), 0.f); }
        *(float4*)&sX[0][w][lane * 4]       = va;
        *(float4*)&sX[0][w][128 + lane * 4] = vb;
    }
    __syncthreads();

    int og = w * 8;
    unsigned long long acc[4][8];
#pragma unroll
    for (int p = 0; p < 4; ++p)
#pragma unroll
        for (int j = 0; j < 8; ++j) acc[p][j] = 0ull;

    for (int k = 0; k < CH; ++k) {
#pragma unroll
        for (int cc = 0; cc < 8; ++cc) {
            int c = k * 8 + cc;
            float4 ua = *(const float4*)&sX[k & 1][cc][lane * 4];
            float4 ub = *(const float4*)&sX[k & 1][cc][128 + lane * 4];
            unsigned long long xp[8] = { pk2(ua.x, ua.x), pk2(ua.y, ua.y),
                                         pk2(ua.z, ua.z), pk2(ua.w, ua.w),
                                         pk2(ub.x, ub.x), pk2(ub.y, ub.y),
                                         pk2(ub.z, ub.z), pk2(ub.w, ub.w) };
            const double2* wp = (const double2*)&sW[c][og];
            double2 w0 = wp[0], w1 = wp[1];
            unsigned long long wq[4] = {
                __double_as_longlong(w0.x), __double_as_longlong(w0.y),
                __double_as_longlong(w1.x), __double_as_longlong(w1.y) };
#pragma unroll
            for (int p = 0; p < 4; ++p)
#pragma unroll
                for (int j = 0; j < 8; ++j)
                    acc[p][j] = f2fma(wq[p], xp[j], acc[p][j]);
        }
        if (k + 1 < CH) {
            float4 va = na, vb = nb;
            if (ACT) { int ch = (k + 1) * 8 + w; float a = sA[ch], d = sD[ch];
                va.x = fmaxf(fmaf(a, va.x, d), 0.f); va.y = fmaxf(fmaf(a, va.y, d), 0.f);
                va.z = fmaxf(fmaf(a, va.z, d), 0.f); va.w = fmaxf(fmaf(a, va.w, d), 0.f);
                vb.x = fmaxf(fmaf(a, vb.x, d), 0.f); vb.y = fmaxf(fmaf(a, vb.y, d), 0.f);
                vb.z = fmaxf(fmaf(a, vb.z, d), 0.f); vb.w = fmaxf(fmaf(a, vb.w, d), 0.f); }
            *(float4*)&sX[(k + 1) & 1][w][lane * 4]       = va;
            *(float4*)&sX[(k + 1) & 1][w][128 + lane * 4] = vb;
            if (k + 2 < CH) {
                na = *(const float4*)(ip + (size_t)((k + 2) * 8 + w) * MPB + lane * 4);
                nb = *(const float4*)(ip + (size_t)((k + 2) * 8 + w) * MPB + 128 + lane * 4);
            }
        }
        __syncthreads();
    }

    float* op = out + (size_t)b * 64 * MPB + mblk * 256;
    int pblk = b * 256 + mblk;
#pragma unroll
    for (int p = 0; p < 4; ++p) {
        float4 a0, a1, b0, b1;
        upk2(acc[p][0], a0.x, a1.x); upk2(acc[p][1], a0.y, a1.y);
        upk2(acc[p][2], a0.z, a1.z); upk2(acc[p][3], a0.w, a1.w);
        upk2(acc[p][4], b0.x, b1.x); upk2(acc[p][5], b0.y, b1.y);
        upk2(acc[p][6], b0.z, b1.z); upk2(acc[p][7], b0.w, b1.w);
        int o0 = og + 2*p, o1 = og + 2*p + 1;
        *(float4*)(op + (size_t)o0 * MPB + lane * 4)       = a0;
        *(float4*)(op + (size_t)o0 * MPB + 128 + lane * 4) = b0;
        *(float4*)(op + (size_t)o1 * MPB + lane * 4)       = a1;
        *(float4*)(op + (size_t)o1 * MPB + 128 + lane * 4) = b1;
        float s0 = (a0.x + a0.y + a0.z + a0.w) + (b0.x + b0.y + b0.z + b0.w);
        float q0 = (a0.x*a0.x + a0.y*a0.y + a0.z*a0.z + a0.w*a0.w)
                 + (b0.x*b0.x + b0.y*b0.y + b0.z*b0.z + b0.w*b0.w);
        float s1 = (a1.x + a1.y + a1.z + a1.w) + (b1.x + b1.y + b1.z + b1.w);
        float q1 = (a1.x*a1.x + a1.y*a1.y + a1.z*a1.z + a1.w*a1.w)
                 + (b1.x*b1.x + b1.y*b1.y + b1.z*b1.z + b1.w*b1.w);
#pragma unroll
        for (int off = 16; off; off >>= 1) {
            s0 += __shfl_xor_sync(0xffffffffu, s0, off);
            q0 += __shfl_xor_sync(0xffffffffu, q0, off);
            s1 += __shfl_xor_sync(0xffffffffu, s1, off);
            q1 += __shfl_xor_sync(0xffffffffu, q1, off);
        }
        if (lane == 0) {
            ps[o0 * NPB + pblk] = s0;  pq[o0 * NPB + pblk] = q0;
            ps[o1 * NPB + pblk] = s1;  pq[o1 * NPB + pblk] = q1;
        }
    }
}

// ---------------- stage-2 stats: NPB partials -> affine coeffs ----------------
__global__ __launch_bounds__(256) void statsfin2_kernel(const float* __restrict__ ps,
                                                        const float* __restrict__ pq,
                                                        const float* __restrict__ gam,
                                                        const float* __restrict__ bet,
                                                        float* __restrict__ aff)
{
    int o = blockIdx.x, tid = threadIdx.x;
    float s = 0.f, q = 0.f;
    for (int i = tid; i < NPB; i += 256) { s += ps[o*NPB + i]; q += pq[o*NPB + i]; }
    __shared__ float rs[256], rq[256];
    rs[tid] = s; rq[tid] = q;
    for (int off = 128; off; off >>= 1) {
        __syncthreads();
        if (tid < off) { rs[tid] += rs[tid + off]; rq[tid] += rq[tid + off]; }
    }
    if (tid == 0) {
        const float invn = 1.f / (float)(NB * MPB);
        float mean = rs[0] * invn;
        float var  = rq[0] * invn - mean * mean;
        float a = gam[o] * rsqrtf(var + 1e-5f);
        aff[o] = a;
        aff[64 + o] = bet[o] - a * mean;
    }
}

// ---------------- residual: x1 = relu(aff2(t2) + relu(aff0(y0))) ----------------
__global__ __launch_bounds__(256) void resid_kernel(const float* __restrict__ y0,
                                                    const float* __restrict__ t2,
                                                    const float* __restrict__ aff0,
                                                    const float* __restrict__ aff2,
                                                    float* __restrict__ x1)
{
    size_t i = (size_t)blockIdx.x * 256 + threadIdx.x;
    int c = (int)((i >> 14) & 63);
    float a0 = aff0[c], d0 = aff0[64+c], a2 = aff2[c], d2 = aff2[64+c];
    float4 y = ((const float4*)y0)[i];
    float4 t = ((const float4*)t2)[i];
    float4 r;
    r.x = fmaxf(fmaf(a2, t.x, d2) + fmaxf(fmaf(a0, y.x, d0), 0.f), 0.f);
    r.y = fmaxf(fmaf(a2, t.y, d2) + fmaxf(fmaf(a0, y.y, d0), 0.f), 0.f);
    r.z = fmaxf(fmaf(a2, t.z, d2) + fmaxf(fmaf(a0, y.z, d0), 0.f), 0.f);
    r.w = fmaxf(fmaf(a2, t.w, d2) + fmaxf(fmaf(a0, y.w, d0), 0.f), 0.f);
    ((float4*)x1)[i] = r;
}

// ---------------- final: feat = max_k relu(aff4(t4) + x1) ----------------
__global__ __launch_bounds__(256) void finalmax_kernel(const float* __restrict__ t4,
                                                       const float* __restrict__ x1,
                                                       const float* __restrict__ aff,
                                                       float* __restrict__ outf)
{
    int g = blockIdx.x * 256 + threadIdx.x;
    int s = g & 2047, o = (g >> 11) & 63, b = g >> 17;
    float a = aff[o], d = aff[64 + o];
    size_t base = (size_t)(b*64 + o) * MPB + s;
    const float* tp = t4 + base;
    const float* xp = x1 + base;
    float m = -1e30f;
#pragma unroll 8
    for (int k = 0; k < 32; ++k)
        m = fmaxf(m, fmaf(a, tp[(size_t)k*2048], d) + xp[(size_t)k*2048]);
    outf[g] = fmaxf(m, 0.f);
}

extern "C" void kernel_launch(void* const* d_in, const int* in_sizes, int n_in,
                              void* d_out, int out_size)
{
    (void)in_sizes; (void)n_in; (void)out_size;
    const float* xyz = (const float*)d_in[0];
    const float* pts = (const float*)d_in[1];
    const float* pw  = (const float*)d_in[2];
    const float* pg  = (const float*)d_in[3];
    const float* pb  = (const float*)d_in[4];
    const float* w1  = (const float*)d_in[5];
    const float* g1  = (const float*)d_in[6];
    const float* b1  = (const float*)d_in[7];
    const float* w2  = (const float*)d_in[8];
    const float* g2  = (const float*)d_in[9];
    const float* b2  = (const float*)d_in[10];

    float *y0, *t1, *t2, *x1, *nx, *ps, *pq, *aff; int* gi;
    cudaGetSymbolAddress((void**)&y0,  g_y0);
    cudaGetSymbolAddress((void**)&t1,  g_t1);
    cudaGetSymbolAddress((void**)&t2,  g_t2);
    cudaGetSymbolAddress((void**)&x1,  g_x1);
    cudaGetSymbolAddress((void**)&nx,  g_nxyz);
    cudaGetSymbolAddress((void**)&gi,  g_idx);
    cudaGetSymbolAddress((void**)&ps,  g_ps);
    cudaGetSymbolAddress((void**)&pq,  g_pq);
    cudaGetSymbolAddress((void**)&aff, g_aff);
    float* out = (float*)d_out;

    cudaFuncSetAttribute(fps_kernel, cudaFuncAttributeMaxDynamicSharedMemorySize,
                         NPTS * (int)sizeof(float4));

    fps_kernel<<<NB * 4, 256, NPTS * sizeof(float4)>>>(xyz, out, nx);
    ball_kernel<<<1024, 256>>>(xyz, nx, gi);
    gather_kernel<<<1024, 256>>>(xyz, pts, gi, nx, t2);

    conv_kernel<32, false><<<1024, 256>>>(t2, pw, nullptr, y0, ps, pq);
    statsfin2_kernel<<<64, 256>>>(ps, pq, pg, pb, aff);

    conv_kernel<64, true><<<1024, 256>>>(y0, w1, aff, t1, ps, pq);
    statsfin2_kernel<<<64, 256>>>(ps, pq, g1, b1, aff + 128);

    conv_kernel<64, true><<<1024, 256>>>(t1, w2, aff + 128, t2, ps, pq);
    statsfin2_kernel<<<64, 256>>>(ps, pq, g2, b2, aff + 256);

    resid_kernel<<<16384, 256>>>(y0, t2, aff, aff + 256, x1);

    conv_kernel<64, false><<<1024, 256>>>(x1, w1 + 4096, nullptr, t1, ps, pq);
    statsfin2_kernel<<<64, 256>>>(ps, pq, g1 + 64, b1 + 64, aff + 384);

    conv_kernel<64, true><<<1024, 256>>>(t1, w2 + 4096, aff + 384, t2, ps, pq);
    statsfin2_kernel<<<64, 256>>>(ps, pq, g2 + 64, b2 + 64, aff + 512);

    finalmax_kernel<<<2048, 256>>>(t2, x1, aff + 512, out + NB*3*NS);
}

// round 15
// speedup vs baseline: 2.0809x; 1.1381x over previous
#include <cuda_runtime.h>
#include <cstdint>

#define NPTS 8192
#define NS   2048
#define NK   32
#define NB   4
#define MPB  65536              /* NK*NS per batch */
#define FSZ  (NB*64*MPB)        /* 16.7M floats per feature buffer */
#define NPB  1024               /* stats partial blocks (4*256) */

__device__ float g_y0[FSZ];
__device__ float g_t1[FSZ];
__device__ float g_t2[FSZ];
__device__ float g_x1[FSZ];
__device__ float g_nxyz[NB*NS*3];
__device__ int   g_idx[NB*NK*NS];
__device__ float g_ps[64*2048];
__device__ float g_pq[64*2048];
__device__ float g_aff[5*128];

static __device__ __forceinline__ unsigned long long pk2(float lo, float hi){
    unsigned long long r; asm("mov.b64 %0,{%1,%2};" : "=l"(r) : "f"(lo), "f"(hi)); return r;
}
static __device__ __forceinline__ void upk2(unsigned long long v, float& lo, float& hi){
    asm("mov.b64 {%0,%1},%2;" : "=f"(lo), "=f"(hi) : "l"(v));
}
static __device__ __forceinline__ void upk2u(unsigned long long v, unsigned& lo, unsigned& hi){
    asm("mov.b64 {%0,%1},%2;" : "=r"(lo), "=r"(hi) : "l"(v));
}
static __device__ __forceinline__ unsigned long long f2fma(unsigned long long a, unsigned long long b, unsigned long long c){
    unsigned long long r; asm("fma.rn.f32x2 %0,%1,%2,%3;" : "=l"(r) : "l"(a), "l"(b), "l"(c)); return r;
}
static __device__ __forceinline__ unsigned long long f2mul(unsigned long long a, unsigned long long b){
    unsigned long long r; asm("mul.rn.f32x2 %0,%1,%2;" : "=l"(r) : "l"(a), "l"(b)); return r;
}
static __device__ __forceinline__ unsigned long long f2add(unsigned long long a, unsigned long long b){
    unsigned long long r; asm("add.rn.f32x2 %0,%1,%2;" : "=l"(r) : "l"(a), "l"(b)); return r;
}
static __device__ __forceinline__ unsigned long long f2sub(unsigned long long a, unsigned long long b){
    unsigned long long r; asm("sub.rn.f32x2 %0,%1,%2;" : "=l"(r) : "l"(a), "l"(b)); return r;
}
static __device__ __forceinline__ unsigned smem_u32(const void* p){
    unsigned a; asm("{ .reg .u64 t; cvta.to.shared.u64 t, %1; cvt.u32.u64 %0, t; }" : "=r"(a) : "l"(p));
    return a;
}
static __device__ __forceinline__ unsigned ctarank(){
    unsigned r; asm("mov.u32 %0, %%cluster_ctarank;" : "=r"(r)); return r;
}
static __device__ __forceinline__ unsigned mapa_u32(unsigned laddr, unsigned r){
    unsigned a; asm("mapa.shared::cluster.u32 %0, %1, %2;" : "=r"(a) : "r"(laddr), "r"(r)); return a;
}
static __device__ __forceinline__ void stc64(unsigned addr, unsigned long long v){
    asm volatile("st.shared::cluster.u64 [%0], %1;" :: "r"(addr), "l"(v) : "memory");
}

// -------- FPS v10: 4-CTA cluster, per-warp fenceless exchange, REDUX combine ----
// Identical protocol to the R13 winner; the only change is the post-poll
// combine: 64-bit 5-level shfl-max replaced by two __reduce_max_sync ops
// (max key, then max of (8191-idx) among key==max) -- provably the same
// max-key-then-min-idx result (exact first-occurrence argmax).
extern __shared__ float4 spts[];    // 8192 float4 = 128KB (orig order)

__global__ __launch_bounds__(256, 1) __cluster_dims__(4, 1, 1)
void fps_kernel(const float* __restrict__ xyz,
                float* __restrict__ outxyz,
                float* __restrict__ nxyz)
{
    int tid = threadIdx.x, lane = tid & 31, wid = tid >> 5;   // 8 warps
    unsigned rank = ctarank();
    int b = blockIdx.x >> 2;
    const float* X = xyz + (size_t)b * 3 * NPTS;

    __shared__ unsigned long long sdata[2][32];   // [parity][global warp 0..31]

    if (tid < 64) ((unsigned long long*)sdata)[tid] = 0ull;   // seq=0 != 1..2048

    // full mirror of all 8192 points (original order)
#pragma unroll 4
    for (int j = 0; j < 32; ++j) {
        int n = tid + j * 256;
        spts[n] = make_float4(X[n], X[NPTS + n], X[2*NPTS + n], 0.f);
    }
    __syncthreads();

    // my quarter: 8 points per thread
    int base = (int)rank * 2048 + tid * 8;
    unsigned long long x2[4], y2[4], z2[4];
    unsigned dist[8];
#pragma unroll
    for (int p = 0; p < 4; ++p) {
        float4 A = spts[base + 2*p];
        float4 B = spts[base + 2*p + 1];
        x2[p] = pk2(A.x, B.x); y2[p] = pk2(A.y, B.y); z2[p] = pk2(A.z, B.z);
        dist[2*p] = __float_as_uint(1e10f); dist[2*p+1] = __float_as_uint(1e10f);
    }

    unsigned slot_base = smem_u32(&sdata[0][0]);
    unsigned gw = rank * 8u + (unsigned)wid;       // global warp id
    unsigned my_off[2] = { slot_base + gw * 8u, slot_base + (32u + gw) * 8u };

    // all CTAs' smem init visible before any remote write
    asm volatile("barrier.cluster.arrive.aligned;" ::: "memory");
    asm volatile("barrier.cluster.wait.aligned;" ::: "memory");

    float cx = X[0], cy = X[NPTS], cz = X[2*NPTS];

    for (int it = 0; it < NS; ++it) {
        if (rank == 0 && tid == 0) {
            outxyz[(b*3 + 0)*NS + it] = cx;
            outxyz[(b*3 + 1)*NS + it] = cy;
            outxyz[(b*3 + 2)*NS + it] = cz;
            nxyz[((size_t)b*NS + it)*3 + 0] = cx;
            nxyz[((size_t)b*NS + it)*3 + 1] = cy;
            nxyz[((size_t)b*NS + it)*3 + 2] = cz;
        }
        unsigned long long cx2 = pk2(cx, cx);
        unsigned long long cy2 = pk2(cy, cy);
        unsigned long long cz2 = pk2(cz, cz);

#pragma unroll
        for (int p = 0; p < 4; ++p) {
            unsigned long long dx = f2sub(x2[p], cx2);
            unsigned long long dy = f2sub(y2[p], cy2);
            unsigned long long dz = f2sub(z2[p], cz2);
            // (dx*dx + dy*dy) + dz*dz -- lane-wise identical to scalar rounding
            unsigned long long s = f2add(f2add(f2mul(dx, dx), f2mul(dy, dy)), f2mul(dz, dz));
            unsigned slo, shi; upk2u(s, slo, shi);
            dist[2*p]   = min(dist[2*p],   slo);
            dist[2*p+1] = min(dist[2*p+1], shi);
        }
        unsigned key = 0u;
#pragma unroll
        for (int j = 0; j < 8; ++j) key = max(key, dist[j]);

        unsigned wmax = __reduce_max_sync(0xffffffffu, key);
        unsigned li = 0xffffffffu;
#pragma unroll
        for (int p = 3; p >= 0; --p) {                 // lo overwrites hi -> min in thread
            if (dist[2*p+1] == wmax) li = (unsigned)(base + 2*p + 1);
            if (dist[2*p]   == wmax) li = (unsigned)(base + 2*p);
        }
        unsigned wmin = __reduce_min_sync(0xffffffffu, li);   // warp min orig idx

        int par = it & 1;
        unsigned tgt = (unsigned)((it + 1) & 0xFFFF);
        if (lane == 0) {
            unsigned long long pack = ((unsigned long long)tgt << 48)
                                    | ((unsigned long long)wmax << 16)
                                    | (unsigned long long)(8191u - (wmin & 0x1FFFu));
            unsigned doff = my_off[par];
#pragma unroll
            for (unsigned r = 0; r < 4; ++r) stc64(mapa_u32(doff, r), pack);
        }
        // poll: lane i watches slot i until all 32 carry seq == it+1
        volatile unsigned long long* vd = (volatile unsigned long long*)&sdata[par][0];
        unsigned long long v;
        do { v = vd[lane]; } while (!__all_sync(0xffffffffu, (unsigned)(v >> 48) == tgt));
        // combine via 2 REDUX: max key, then max (8191-idx) among key==max
        unsigned k  = (unsigned)(v >> 16);             // exact 32-bit key field
        unsigned kg = __reduce_max_sync(0xffffffffu, k);
        unsigned cand = (k == kg) ? (unsigned)(v & 0x1FFFull) : 0u;
        unsigned cm = __reduce_max_sync(0xffffffffu, cand);
        unsigned widx = 8191u - cm;
        float4 cc = spts[widx];
        cx = cc.x; cy = cc.y; cz = cc.z;
    }
    // keep CTAs resident until all have finished the protocol
    asm volatile("barrier.cluster.arrive.aligned;" ::: "memory");
    asm volatile("barrier.cluster.wait.aligned;" ::: "memory");
}

// ---------------- ball query: one warp per center ----------------
__global__ __launch_bounds__(256) void ball_kernel(const float* __restrict__ xyz,
                                                   const float* __restrict__ nxyz,
                                                   int* __restrict__ gidx)
{
    __shared__ int sbuf[8][32];
    int w = threadIdx.x >> 5, lane = threadIdx.x & 31;
    int gid = blockIdx.x * 8 + w;
    int b = gid >> 11, s = gid & 2047;
    const float* X = xyz + (size_t)b * 3 * NPTS;

    float cx = nxyz[gid*3], cy = nxyz[gid*3 + 1], cz = nxyz[gid*3 + 2];
    float cc = __fadd_rn(__fadd_rn(__fmul_rn(cx,cx), __fmul_rn(cy,cy)), __fmul_rn(cz,cz));
    const float R2 = (float)(0.1 * 0.1);

    int cnt = 0;
    for (int base = 0; base < NPTS; base += 32) {
        int n = base + lane;
        float px = X[n], py = X[NPTS + n], pz = X[2*NPTS + n];
        float pp  = __fadd_rn(__fadd_rn(__fmul_rn(px,px), __fmul_rn(py,py)), __fmul_rn(pz,pz));
        float dot = __fadd_rn(__fadd_rn(__fmul_rn(cx,px), __fmul_rn(cy,py)), __fmul_rn(cz,pz));
        float sqr = __fadd_rn(__fadd_rn(cc, pp), -__fmul_rn(2.f, dot));
        bool hit = (sqr <= R2);
        unsigned m = __ballot_sync(0xffffffffu, hit);
        if (m) {
            int rank = cnt + __popc(m & ((1u << lane) - 1u));
            if (hit && rank < 32) sbuf[w][rank] = n;
            cnt += __popc(m);
            if (cnt >= 32) break;
        }
    }
    __syncwarp();
    int first = sbuf[w][0];
    int my = (lane < cnt) ? sbuf[w][lane] : first;
    gidx[((size_t)(b*32 + lane))*2048 + s] = my;
}

// ---------------- gather + center-subtract + concat ----------------
__global__ __launch_bounds__(256) void gather_kernel(const float* __restrict__ xyz,
                                                     const float* __restrict__ pts,
                                                     const int* __restrict__ gidx,
                                                     const float* __restrict__ nxyz,
                                                     float* __restrict__ xin)
{
    int g = blockIdx.x * 256 + threadIdx.x;
    int s = g & 2047, k = (g >> 11) & 31, b = g >> 16;
    int id = gidx[((size_t)(b*32 + k))*2048 + s];
    const float* X = xyz + (size_t)b * 3 * NPTS;
    const float* P = pts + (size_t)b * 29 * NPTS;
    size_t ob = (size_t)b * 32 * MPB + (size_t)k * 2048 + s;
#pragma unroll
    for (int c = 0; c < 3; ++c)
        xin[ob + (size_t)c * MPB] = X[c*NPTS + id] - nxyz[((size_t)(b*2048 + s))*3 + c];
#pragma unroll
    for (int c = 0; c < 29; ++c)
        xin[ob + (size_t)(3 + c) * MPB] = P[c*NPTS + id];
}

// ---------------- conv v3: 256 pts/block, 8 pts/thread, fused stats ----------------
template<int CIN, bool ACT>
__global__ __launch_bounds__(256) void conv_kernel(const float* __restrict__ in,
                                                   const float* __restrict__ W,
                                                   const float* __restrict__ aff,
                                                   float* __restrict__ out,
                                                   float* __restrict__ ps,
                                                   float* __restrict__ pq)
{
    constexpr int CH = CIN / 8;
    __shared__ float sW[CIN][64];
    __shared__ float sX[2][8][256];
    __shared__ float sA[64], sD[64];
    int tid = threadIdx.x, lane = tid & 31, w = tid >> 5;
    int b = blockIdx.x >> 8, mblk = blockIdx.x & 255;
    const float* ip = in + (size_t)b * CIN * MPB + mblk * 256;

    for (int i = tid; i < CIN * 64; i += 256)
        sW[i >> 6][i & 63] = W[(i & 63) * CIN + (i >> 6)];
    if (ACT) for (int i = tid; i < CIN; i += 256) { sA[i] = aff[i]; sD[i] = aff[64 + i]; }

    float4 xa = *(const float4*)(ip + (size_t)w * MPB + lane * 4);
    float4 xb = *(const float4*)(ip + (size_t)w * MPB + 128 + lane * 4);
    float4 na, nb;
    if (CH > 1) {
        na = *(const float4*)(ip + (size_t)(8 + w) * MPB + lane * 4);
        nb = *(const float4*)(ip + (size_t)(8 + w) * MPB + 128 + lane * 4);
    }
    __syncthreads();
    {
        float4 va = xa, vb = xb;
        if (ACT) { float a = sA[w], d = sD[w];
            va.x = fmaxf(fmaf(a, va.x, d), 0.f); va.y = fmaxf(fmaf(a, va.y, d), 0.f);
            va.z = fmaxf(fmaf(a, va.z, d), 0.f); va.w = fmaxf(fmaf(a, va.w, d), 0.f);
            vb.x = fmaxf(fmaf(a, vb.x, d), 0.f); vb.y = fmaxf(fmaf(a, vb.y, d), 0.f);
            vb.z = fmaxf(fmaf(a, vb.z, d), 0.f); vb.w = fmaxf(fmaf(a, vb.w, d), 0.f); }
        *(float4*)&sX[0][w][lane * 4]       = va;
        *(float4*)&sX[0][w][128 + lane * 4] = vb;
    }
    __syncthreads();

    int og = w * 8;
    unsigned long long acc[4][8];
#pragma unroll
    for (int p = 0; p < 4; ++p)
#pragma unroll
        for (int j = 0; j < 8; ++j) acc[p][j] = 0ull;

    for (int k = 0; k < CH; ++k) {
#pragma unroll
        for (int cc = 0; cc < 8; ++cc) {
            int c = k * 8 + cc;
            float4 ua = *(const float4*)&sX[k & 1][cc][lane * 4];
            float4 ub = *(const float4*)&sX[k & 1][cc][128 + lane * 4];
            unsigned long long xp[8] = { pk2(ua.x, ua.x), pk2(ua.y, ua.y),
                                         pk2(ua.z, ua.z), pk2(ua.w, ua.w),
                                         pk2(ub.x, ub.x), pk2(ub.y, ub.y),
                                         pk2(ub.z, ub.z), pk2(ub.w, ub.w) };
            const double2* wp = (const double2*)&sW[c][og];
            double2 w0 = wp[0], w1 = wp[1];
            unsigned long long wq[4] = {
                __double_as_longlong(w0.x), __double_as_longlong(w0.y),
                __double_as_longlong(w1.x), __double_as_longlong(w1.y) };
#pragma unroll
            for (int p = 0; p < 4; ++p)
#pragma unroll
                for (int j = 0; j < 8; ++j)
                    acc[p][j] = f2fma(wq[p], xp[j], acc[p][j]);
        }
        if (k + 1 < CH) {
            float4 va = na, vb = nb;
            if (ACT) { int ch = (k + 1) * 8 + w; float a = sA[ch], d = sD[ch];
                va.x = fmaxf(fmaf(a, va.x, d), 0.f); va.y = fmaxf(fmaf(a, va.y, d), 0.f);
                va.z = fmaxf(fmaf(a, va.z, d), 0.f); va.w = fmaxf(fmaf(a, va.w, d), 0.f);
                vb.x = fmaxf(fmaf(a, vb.x, d), 0.f); vb.y = fmaxf(fmaf(a, vb.y, d), 0.f);
                vb.z = fmaxf(fmaf(a, vb.z, d), 0.f); vb.w = fmaxf(fmaf(a, vb.w, d), 0.f); }
            *(float4*)&sX[(k + 1) & 1][w][lane * 4]       = va;
            *(float4*)&sX[(k + 1) & 1][w][128 + lane * 4] = vb;
            if (k + 2 < CH) {
                na = *(const float4*)(ip + (size_t)((k + 2) * 8 + w) * MPB + lane * 4);
                nb = *(const float4*)(ip + (size_t)((k + 2) * 8 + w) * MPB + 128 + lane * 4);
            }
        }
        __syncthreads();
    }

    float* op = out + (size_t)b * 64 * MPB + mblk * 256;
    int pblk = b * 256 + mblk;
#pragma unroll
    for (int p = 0; p < 4; ++p) {
        float4 a0, a1, b0, b1;
        upk2(acc[p][0], a0.x, a1.x); upk2(acc[p][1], a0.y, a1.y);
        upk2(acc[p][2], a0.z, a1.z); upk2(acc[p][3], a0.w, a1.w);
        upk2(acc[p][4], b0.x, b1.x); upk2(acc[p][5], b0.y, b1.y);
        upk2(acc[p][6], b0.z, b1.z); upk2(acc[p][7], b0.w, b1.w);
        int o0 = og + 2*p, o1 = og + 2*p + 1;
        *(float4*)(op + (size_t)o0 * MPB + lane * 4)       = a0;
        *(float4*)(op + (size_t)o0 * MPB + 128 + lane * 4) = b0;
        *(float4*)(op + (size_t)o1 * MPB + lane * 4)       = a1;
        *(float4*)(op + (size_t)o1 * MPB + 128 + lane * 4) = b1;
        float s0 = (a0.x + a0.y + a0.z + a0.w) + (b0.x + b0.y + b0.z + b0.w);
        float q0 = (a0.x*a0.x + a0.y*a0.y + a0.z*a0.z + a0.w*a0.w)
                 + (b0.x*b0.x + b0.y*b0.y + b0.z*b0.z + b0.w*b0.w);
        float s1 = (a1.x + a1.y + a1.z + a1.w) + (b1.x + b1.y + b1.z + b1.w);
        float q1 = (a1.x*a1.x + a1.y*a1.y + a1.z*a1.z + a1.w*a1.w)
                 + (b1.x*b1.x + b1.y*b1.y + b1.z*b1.z + b1.w*b1.w);
#pragma unroll
        for (int off = 16; off; off >>= 1) {
            s0 += __shfl_xor_sync(0xffffffffu, s0, off);
            q0 += __shfl_xor_sync(0xffffffffu, q0, off);
            s1 += __shfl_xor_sync(0xffffffffu, s1, off);
            q1 += __shfl_xor_sync(0xffffffffu, q1, off);
        }
        if (lane == 0) {
            ps[o0 * NPB + pblk] = s0;  pq[o0 * NPB + pblk] = q0;
            ps[o1 * NPB + pblk] = s1;  pq[o1 * NPB + pblk] = q1;
        }
    }
}

// ---------------- stage-2 stats: NPB partials -> affine coeffs ----------------
__global__ __launch_bounds__(256) void statsfin2_kernel(const float* __restrict__ ps,
                                                        const float* __restrict__ pq,
                                                        const float* __restrict__ gam,
                                                        const float* __restrict__ bet,
                                                        float* __restrict__ aff)
{
    int o = blockIdx.x, tid = threadIdx.x;
    float s = 0.f, q = 0.f;
    for (int i = tid; i < NPB; i += 256) { s += ps[o*NPB + i]; q += pq[o*NPB + i]; }
    __shared__ float rs[256], rq[256];
    rs[tid] = s; rq[tid] = q;
    for (int off = 128; off; off >>= 1) {
        __syncthreads();
        if (tid < off) { rs[tid] += rs[tid + off]; rq[tid] += rq[tid + off]; }
    }
    if (tid == 0) {
        const float invn = 1.f / (float)(NB * MPB);
        float mean = rs[0] * invn;
        float var  = rq[0] * invn - mean * mean;
        float a = gam[o] * rsqrtf(var + 1e-5f);
        aff[o] = a;
        aff[64 + o] = bet[o] - a * mean;
    }
}

// ---------------- residual: x1 = relu(aff2(t2) + relu(aff0(y0))) ----------------
__global__ __launch_bounds__(256) void resid_kernel(const float* __restrict__ y0,
                                                    const float* __restrict__ t2,
                                                    const float* __restrict__ aff0,
                                                    const float* __restrict__ aff2,
                                                    float* __restrict__ x1)
{
    size_t i = (size_t)blockIdx.x * 256 + threadIdx.x;
    int c = (int)((i >> 14) & 63);
    float a0 = aff0[c], d0 = aff0[64+c], a2 = aff2[c], d2 = aff2[64+c];
    float4 y = ((const float4*)y0)[i];
    float4 t = ((const float4*)t2)[i];
    float4 r;
    r.x = fmaxf(fmaf(a2, t.x, d2) + fmaxf(fmaf(a0, y.x, d0), 0.f), 0.f);
    r.y = fmaxf(fmaf(a2, t.y, d2) + fmaxf(fmaf(a0, y.y, d0), 0.f), 0.f);
    r.z = fmaxf(fmaf(a2, t.z, d2) + fmaxf(fmaf(a0, y.z, d0), 0.f), 0.f);
    r.w = fmaxf(fmaf(a2, t.w, d2) + fmaxf(fmaf(a0, y.w, d0), 0.f), 0.f);
    ((float4*)x1)[i] = r;
}

// ---------------- final: feat = max_k relu(aff4(t4) + x1) ----------------
__global__ __launch_bounds__(256) void finalmax_kernel(const float* __restrict__ t4,
                                                       const float* __restrict__ x1,
                                                       const float* __restrict__ aff,
                                                       float* __restrict__ outf)
{
    int g = blockIdx.x * 256 + threadIdx.x;
    int s = g & 2047, o = (g >> 11) & 63, b = g >> 17;
    float a = aff[o], d = aff[64 + o];
    size_t base = (size_t)(b*64 + o) * MPB + s;
    const float* tp = t4 + base;
    const float* xp = x1 + base;
    float m = -1e30f;
#pragma unroll 8
    for (int k = 0; k < 32; ++k)
        m = fmaxf(m, fmaf(a, tp[(size_t)k*2048], d) + xp[(size_t)k*2048]);
    outf[g] = fmaxf(m, 0.f);
}

extern "C" void kernel_launch(void* const* d_in, const int* in_sizes, int n_in,
                              void* d_out, int out_size)
{
    (void)in_sizes; (void)n_in; (void)out_size;
    const float* xyz = (const float*)d_in[0];
    const float* pts = (const float*)d_in[1];
    const float* pw  = (const float*)d_in[2];
    const float* pg  = (const float*)d_in[3];
    const float* pb  = (const float*)d_in[4];
    const float* w1  = (const float*)d_in[5];
    const float* g1  = (const float*)d_in[6];
    const float* b1  = (const float*)d_in[7];
    const float* w2  = (const float*)d_in[8];
    const float* g2  = (const float*)d_in[9];
    const float* b2  = (const float*)d_in[10];

    float *y0, *t1, *t2, *x1, *nx, *ps, *pq, *aff; int* gi;
    cudaGetSymbolAddress((void**)&y0,  g_y0);
    cudaGetSymbolAddress((void**)&t1,  g_t1);
    cudaGetSymbolAddress((void**)&t2,  g_t2);
    cudaGetSymbolAddress((void**)&x1,  g_x1);
    cudaGetSymbolAddress((void**)&nx,  g_nxyz);
    cudaGetSymbolAddress((void**)&gi,  g_idx);
    cudaGetSymbolAddress((void**)&ps,  g_ps);
    cudaGetSymbolAddress((void**)&pq,  g_pq);
    cudaGetSymbolAddress((void**)&aff, g_aff);
    float* out = (float*)d_out;

    cudaFuncSetAttribute(fps_kernel, cudaFuncAttributeMaxDynamicSharedMemorySize,
                         NPTS * (int)sizeof(float4));

    fps_kernel<<<NB * 4, 256, NPTS * sizeof(float4)>>>(xyz, out, nx);
    ball_kernel<<<1024, 256>>>(xyz, nx, gi);
    gather_kernel<<<1024, 256>>>(xyz, pts, gi, nx, t2);

    conv_kernel<32, false><<<1024, 256>>>(t2, pw, nullptr, y0, ps, pq);
    statsfin2_kernel<<<64, 256>>>(ps, pq, pg, pb, aff);

    conv_kernel<64, true><<<1024, 256>>>(y0, w1, aff, t1, ps, pq);
    statsfin2_kernel<<<64, 256>>>(ps, pq, g1, b1, aff + 128);

    conv_kernel<64, true><<<1024, 256>>>(t1, w2, aff + 128, t2, ps, pq);
    statsfin2_kernel<<<64, 256>>>(ps, pq, g2, b2, aff + 256);

    resid_kernel<<<16384, 256>>>(y0, t2, aff, aff + 256, x1);

    conv_kernel<64, false><<<1024, 256>>>(x1, w1 + 4096, nullptr, t1, ps, pq);
    statsfin2_kernel<<<64, 256>>>(ps, pq, g1 + 64, b1 + 64, aff + 384);

    conv_kernel<64, true><<<1024, 256>>>(t1, w2 + 4096, aff + 384, t2, ps, pq);
    statsfin2_kernel<<<64, 256>>>(ps, pq, g2 + 64, b2 + 64, aff + 512);

    finalmax_kernel<<<2048, 256>>>(t2, x1, aff + 512, out + NB*3*NS);
}

// round 16
// speedup vs baseline: 2.0891x; 1.0040x over previous
#include <cuda_runtime.h>
#include <cstdint>

#define NPTS 8192
#define NS   2048
#define NK   32
#define NB   4
#define MPB  65536              /* NK*NS per batch */
#define FSZ  (NB*64*MPB)        /* 16.7M floats per feature buffer */
#define NPB  1024               /* stats partial blocks (4*256) */

__device__ float g_y0[FSZ];
__device__ float g_t1[FSZ];
__device__ float g_t2[FSZ];
__device__ float g_x1[FSZ];
__device__ float g_nxyz[NB*NS*3];
__device__ int   g_idx[NB*NK*NS];
__device__ float g_ps[64*2048];
__device__ float g_pq[64*2048];
__device__ float g_aff[5*128];

static __device__ __forceinline__ unsigned long long pk2(float lo, float hi){
    unsigned long long r; asm("mov.b64 %0,{%1,%2};" : "=l"(r) : "f"(lo), "f"(hi)); return r;
}
static __device__ __forceinline__ void upk2(unsigned long long v, float& lo, float& hi){
    asm("mov.b64 {%0,%1},%2;" : "=f"(lo), "=f"(hi) : "l"(v));
}
static __device__ __forceinline__ void upk2u(unsigned long long v, unsigned& lo, unsigned& hi){
    asm("mov.b64 {%0,%1},%2;" : "=r"(lo), "=r"(hi) : "l"(v));
}
static __device__ __forceinline__ unsigned long long f2fma(unsigned long long a, unsigned long long b, unsigned long long c){
    unsigned long long r; asm("fma.rn.f32x2 %0,%1,%2,%3;" : "=l"(r) : "l"(a), "l"(b), "l"(c)); return r;
}
static __device__ __forceinline__ unsigned long long f2mul(unsigned long long a, unsigned long long b){
    unsigned long long r; asm("mul.rn.f32x2 %0,%1,%2;" : "=l"(r) : "l"(a), "l"(b)); return r;
}
static __device__ __forceinline__ unsigned long long f2add(unsigned long long a, unsigned long long b){
    unsigned long long r; asm("add.rn.f32x2 %0,%1,%2;" : "=l"(r) : "l"(a), "l"(b)); return r;
}
static __device__ __forceinline__ unsigned long long f2sub(unsigned long long a, unsigned long long b){
    unsigned long long r; asm("sub.rn.f32x2 %0,%1,%2;" : "=l"(r) : "l"(a), "l"(b)); return r;
}
static __device__ __forceinline__ unsigned smem_u32(const void* p){
    unsigned a; asm("{ .reg .u64 t; cvta.to.shared.u64 t, %1; cvt.u32.u64 %0, t; }" : "=r"(a) : "l"(p));
    return a;
}
static __device__ __forceinline__ unsigned ctarank(){
    unsigned r; asm("mov.u32 %0, %%cluster_ctarank;" : "=r"(r)); return r;
}
static __device__ __forceinline__ unsigned mapa_u32(unsigned laddr, unsigned r){
    unsigned a; asm("mapa.shared::cluster.u32 %0, %1, %2;" : "=r"(a) : "r"(laddr), "r"(r)); return a;
}
static __device__ __forceinline__ void stc64(unsigned addr, unsigned long long v){
    asm volatile("st.shared::cluster.u64 [%0], %1;" :: "r"(addr), "l"(v) : "memory");
}

// -------- FPS v11: 8-CTA cluster, per-warp fenceless exchange, REDUX combine ----
// Same proven protocol as R13/R14, scaled to 8 CTAs x 1024 points (4/thread).
// 64 publish slots; each lane polls 2; combine = per-lane max-of-2 + 2 REDUX
// (max key, then max (8191-idx) among key==max) -> exact first-occurrence.
extern __shared__ float4 spts[];    // 8192 float4 = 128KB (orig order)

__global__ __launch_bounds__(256, 1) __cluster_dims__(8, 1, 1)
void fps_kernel(const float* __restrict__ xyz,
                float* __restrict__ outxyz,
                float* __restrict__ nxyz)
{
    int tid = threadIdx.x, lane = tid & 31, wid = tid >> 5;   // 8 warps
    unsigned rank = ctarank();
    int b = blockIdx.x >> 3;
    const float* X = xyz + (size_t)b * 3 * NPTS;

    __shared__ unsigned long long sdata[2][64];   // [parity][global warp 0..63]

    if (tid < 128) ((unsigned long long*)sdata)[tid] = 0ull;  // seq=0 != 1..2048

    // full mirror of all 8192 points (original order)
#pragma unroll 4
    for (int j = 0; j < 32; ++j) {
        int n = tid + j * 256;
        spts[n] = make_float4(X[n], X[NPTS + n], X[2*NPTS + n], 0.f);
    }
    __syncthreads();

    // my eighth: 4 points per thread
    int base = (int)rank * 1024 + tid * 4;
    unsigned long long x2[2], y2[2], z2[2];
    unsigned dist[4];
#pragma unroll
    for (int p = 0; p < 2; ++p) {
        float4 A = spts[base + 2*p];
        float4 B = spts[base + 2*p + 1];
        x2[p] = pk2(A.x, B.x); y2[p] = pk2(A.y, B.y); z2[p] = pk2(A.z, B.z);
        dist[2*p] = __float_as_uint(1e10f); dist[2*p+1] = __float_as_uint(1e10f);
    }

    unsigned slot_base = smem_u32(&sdata[0][0]);
    unsigned gw = rank * 8u + (unsigned)wid;       // global warp id 0..63
    unsigned my_off[2] = { slot_base + gw * 8u, slot_base + (64u + gw) * 8u };

    // all CTAs' smem init visible before any remote write
    asm volatile("barrier.cluster.arrive.aligned;" ::: "memory");
    asm volatile("barrier.cluster.wait.aligned;" ::: "memory");

    float cx = X[0], cy = X[NPTS], cz = X[2*NPTS];

    for (int it = 0; it < NS; ++it) {
        if (rank == 0 && tid == 0) {
            outxyz[(b*3 + 0)*NS + it] = cx;
            outxyz[(b*3 + 1)*NS + it] = cy;
            outxyz[(b*3 + 2)*NS + it] = cz;
            nxyz[((size_t)b*NS + it)*3 + 0] = cx;
            nxyz[((size_t)b*NS + it)*3 + 1] = cy;
            nxyz[((size_t)b*NS + it)*3 + 2] = cz;
        }
        unsigned long long cx2 = pk2(cx, cx);
        unsigned long long cy2 = pk2(cy, cy);
        unsigned long long cz2 = pk2(cz, cz);

#pragma unroll
        for (int p = 0; p < 2; ++p) {
            unsigned long long dx = f2sub(x2[p], cx2);
            unsigned long long dy = f2sub(y2[p], cy2);
            unsigned long long dz = f2sub(z2[p], cz2);
            // (dx*dx + dy*dy) + dz*dz -- lane-wise identical to scalar rounding
            unsigned long long s = f2add(f2add(f2mul(dx, dx), f2mul(dy, dy)), f2mul(dz, dz));
            unsigned slo, shi; upk2u(s, slo, shi);
            dist[2*p]   = min(dist[2*p],   slo);
            dist[2*p+1] = min(dist[2*p+1], shi);
        }
        unsigned key = max(max(dist[0], dist[1]), max(dist[2], dist[3]));

        unsigned wmax = __reduce_max_sync(0xffffffffu, key);
        unsigned li = 0xffffffffu;
#pragma unroll
        for (int p = 1; p >= 0; --p) {                 // lo overwrites hi -> min in thread
            if (dist[2*p+1] == wmax) li = (unsigned)(base + 2*p + 1);
            if (dist[2*p]   == wmax) li = (unsigned)(base + 2*p);
        }
        unsigned wmin = __reduce_min_sync(0xffffffffu, li);   // warp min orig idx

        int par = it & 1;
        unsigned tgt = (unsigned)((it + 1) & 0xFFFF);
        if (lane == 0) {
            unsigned long long pack = ((unsigned long long)tgt << 48)
                                    | ((unsigned long long)wmax << 16)
                                    | (unsigned long long)(8191u - (wmin & 0x1FFFu));
            unsigned doff = my_off[par];
#pragma unroll
            for (unsigned r = 0; r < 8; ++r) stc64(mapa_u32(doff, r), pack);
        }
        // poll: lane i watches slots i and i+32 until all 64 carry seq == it+1
        volatile unsigned long long* vd = (volatile unsigned long long*)&sdata[par][0];
        unsigned long long v0, v1;
        do { v0 = vd[lane]; v1 = vd[lane + 32]; }
        while (!__all_sync(0xffffffffu,
                           ((unsigned)(v0 >> 48) == tgt) && ((unsigned)(v1 >> 48) == tgt)));
        // combine: max key, then max (8191-idx) among key==max
        unsigned k0 = (unsigned)(v0 >> 16), k1 = (unsigned)(v1 >> 16);
        unsigned kg = __reduce_max_sync(0xffffffffu, max(k0, k1));
        unsigned cand = max((k0 == kg) ? (unsigned)(v0 & 0x1FFFull) : 0u,
                            (k1 == kg) ? (unsigned)(v1 & 0x1FFFull) : 0u);
        unsigned cm = __reduce_max_sync(0xffffffffu, cand);
        unsigned widx = 8191u - cm;
        float4 cc = spts[widx];
        cx = cc.x; cy = cc.y; cz = cc.z;
    }
    // keep CTAs resident until all have finished the protocol
    asm volatile("barrier.cluster.arrive.aligned;" ::: "memory");
    asm volatile("barrier.cluster.wait.aligned;" ::: "memory");
}

// ---------------- ball query: one warp per center ----------------
__global__ __launch_bounds__(256) void ball_kernel(const float* __restrict__ xyz,
                                                   const float* __restrict__ nxyz,
                                                   int* __restrict__ gidx)
{
    __shared__ int sbuf[8][32];
    int w = threadIdx.x >> 5, lane = threadIdx.x & 31;
    int gid = blockIdx.x * 8 + w;
    int b = gid >> 11, s = gid & 2047;
    const float* X = xyz + (size_t)b * 3 * NPTS;

    float cx = nxyz[gid*3], cy = nxyz[gid*3 + 1], cz = nxyz[gid*3 + 2];
    float cc = __fadd_rn(__fadd_rn(__fmul_rn(cx,cx), __fmul_rn(cy,cy)), __fmul_rn(cz,cz));
    const float R2 = (float)(0.1 * 0.1);

    int cnt = 0;
    for (int base = 0; base < NPTS; base += 32) {
        int n = base + lane;
        float px = X[n], py = X[NPTS + n], pz = X[2*NPTS + n];
        float pp  = __fadd_rn(__fadd_rn(__fmul_rn(px,px), __fmul_rn(py,py)), __fmul_rn(pz,pz));
        float dot = __fadd_rn(__fadd_rn(__fmul_rn(cx,px), __fmul_rn(cy,py)), __fmul_rn(cz,pz));
        float sqr = __fadd_rn(__fadd_rn(cc, pp), -__fmul_rn(2.f, dot));
        bool hit = (sqr <= R2);
        unsigned m = __ballot_sync(0xffffffffu, hit);
        if (m) {
            int rank = cnt + __popc(m & ((1u << lane) - 1u));
            if (hit && rank < 32) sbuf[w][rank] = n;
            cnt += __popc(m);
            if (cnt >= 32) break;
        }
    }
    __syncwarp();
    int first = sbuf[w][0];
    int my = (lane < cnt) ? sbuf[w][lane] : first;
    gidx[((size_t)(b*32 + lane))*2048 + s] = my;
}

// ---------------- gather + center-subtract + concat ----------------
__global__ __launch_bounds__(256) void gather_kernel(const float* __restrict__ xyz,
                                                     const float* __restrict__ pts,
                                                     const int* __restrict__ gidx,
                                                     const float* __restrict__ nxyz,
                                                     float* __restrict__ xin)
{
    int g = blockIdx.x * 256 + threadIdx.x;
    int s = g & 2047, k = (g >> 11) & 31, b = g >> 16;
    int id = gidx[((size_t)(b*32 + k))*2048 + s];
    const float* X = xyz + (size_t)b * 3 * NPTS;
    const float* P = pts + (size_t)b * 29 * NPTS;
    size_t ob = (size_t)b * 32 * MPB + (size_t)k * 2048 + s;
#pragma unroll
    for (int c = 0; c < 3; ++c)
        xin[ob + (size_t)c * MPB] = X[c*NPTS + id] - nxyz[((size_t)(b*2048 + s))*3 + c];
#pragma unroll
    for (int c = 0; c < 29; ++c)
        xin[ob + (size_t)(3 + c) * MPB] = P[c*NPTS + id];
}

// ---------------- conv v3: 256 pts/block, 8 pts/thread, fused stats ----------------
template<int CIN, bool ACT>
__global__ __launch_bounds__(256) void conv_kernel(const float* __restrict__ in,
                                                   const float* __restrict__ W,
                                                   const float* __restrict__ aff,
                                                   float* __restrict__ out,
                                                   float* __restrict__ ps,
                                                   float* __restrict__ pq)
{
    constexpr int CH = CIN / 8;
    __shared__ float sW[CIN][64];
    __shared__ float sX[2][8][256];
    __shared__ float sA[64], sD[64];
    int tid = threadIdx.x, lane = tid & 31, w = tid >> 5;
    int b = blockIdx.x >> 8, mblk = blockIdx.x & 255;
    const float* ip = in + (size_t)b * CIN * MPB + mblk * 256;

    for (int i = tid; i < CIN * 64; i += 256)
        sW[i >> 6][i & 63] = W[(i & 63) * CIN + (i >> 6)];
    if (ACT) for (int i = tid; i < CIN; i += 256) { sA[i] = aff[i]; sD[i] = aff[64 + i]; }

    float4 xa = *(const float4*)(ip + (size_t)w * MPB + lane * 4);
    float4 xb = *(const float4*)(ip + (size_t)w * MPB + 128 + lane * 4);
    float4 na, nb;
    if (CH > 1) {
        na = *(const float4*)(ip + (size_t)(8 + w) * MPB + lane * 4);
        nb = *(const float4*)(ip + (size_t)(8 + w) * MPB + 128 + lane * 4);
    }
    __syncthreads();
    {
        float4 va = xa, vb = xb;
        if (ACT) { float a = sA[w], d = sD[w];
            va.x = fmaxf(fmaf(a, va.x, d), 0.f); va.y = fmaxf(fmaf(a, va.y, d), 0.f);
            va.z = fmaxf(fmaf(a, va.z, d), 0.f); va.w = fmaxf(fmaf(a, va.w, d), 0.f);
            vb.x = fmaxf(fmaf(a, vb.x, d), 0.f); vb.y = fmaxf(fmaf(a, vb.y, d), 0.f);
            vb.z = fmaxf(fmaf(a, vb.z, d), 0.f); vb.w = fmaxf(fmaf(a, vb.w, d), 0.f); }
        *(float4*)&sX[0][w][lane * 4]       = va;
        *(float4*)&sX[0][w][128 + lane * 4] = vb;
    }
    __syncthreads();

    int og = w * 8;
    unsigned long long acc[4][8];
#pragma unroll
    for (int p = 0; p < 4; ++p)
#pragma unroll
        for (int j = 0; j < 8; ++j) acc[p][j] = 0ull;

    for (int k = 0; k < CH; ++k) {
#pragma unroll
        for (int cc = 0; cc < 8; ++cc) {
            int c = k * 8 + cc;
            float4 ua = *(const float4*)&sX[k & 1][cc][lane * 4];
            float4 ub = *(const float4*)&sX[k & 1][cc][128 + lane * 4];
            unsigned long long xp[8] = { pk2(ua.x, ua.x), pk2(ua.y, ua.y),
                                         pk2(ua.z, ua.z), pk2(ua.w, ua.w),
                                         pk2(ub.x, ub.x), pk2(ub.y, ub.y),
                                         pk2(ub.z, ub.z), pk2(ub.w, ub.w) };
            const double2* wp = (const double2*)&sW[c][og];
            double2 w0 = wp[0], w1 = wp[1];
            unsigned long long wq[4] = {
                __double_as_longlong(w0.x), __double_as_longlong(w0.y),
                __double_as_longlong(w1.x), __double_as_longlong(w1.y) };
#pragma unroll
            for (int p = 0; p < 4; ++p)
#pragma unroll
                for (int j = 0; j < 8; ++j)
                    acc[p][j] = f2fma(wq[p], xp[j], acc[p][j]);
        }
        if (k + 1 < CH) {
            float4 va = na, vb = nb;
            if (ACT) { int ch = (k + 1) * 8 + w; float a = sA[ch], d = sD[ch];
                va.x = fmaxf(fmaf(a, va.x, d), 0.f); va.y = fmaxf(fmaf(a, va.y, d), 0.f);
                va.z = fmaxf(fmaf(a, va.z, d), 0.f); va.w = fmaxf(fmaf(a, va.w, d), 0.f);
                vb.x = fmaxf(fmaf(a, vb.x, d), 0.f); vb.y = fmaxf(fmaf(a, vb.y, d), 0.f);
                vb.z = fmaxf(fmaf(a, vb.z, d), 0.f); vb.w = fmaxf(fmaf(a, vb.w, d), 0.f); }
            *(float4*)&sX[(k + 1) & 1][w][lane * 4]       = va;
            *(float4*)&sX[(k + 1) & 1][w][128 + lane * 4] = vb;
            if (k + 2 < CH) {
                na = *(const float4*)(ip + (size_t)((k + 2) * 8 + w) * MPB + lane * 4);
                nb = *(const float4*)(ip + (size_t)((k + 2) * 8 + w) * MPB + 128 + lane * 4);
            }
        }
        __syncthreads();
    }

    float* op = out + (size_t)b * 64 * MPB + mblk * 256;
    int pblk = b * 256 + mblk;
#pragma unroll
    for (int p = 0; p < 4; ++p) {
        float4 a0, a1, b0, b1;
        upk2(acc[p][0], a0.x, a1.x); upk2(acc[p][1], a0.y, a1.y);
        upk2(acc[p][2], a0.z, a1.z); upk2(acc[p][3], a0.w, a1.w);
        upk2(acc[p][4], b0.x, b1.x); upk2(acc[p][5], b0.y, b1.y);
        upk2(acc[p][6], b0.z, b1.z); upk2(acc[p][7], b0.w, b1.w);
        int o0 = og + 2*p, o1 = og + 2*p + 1;
        *(float4*)(op + (size_t)o0 * MPB + lane * 4)       = a0;
        *(float4*)(op + (size_t)o0 * MPB + 128 + lane * 4) = b0;
        *(float4*)(op + (size_t)o1 * MPB + lane * 4)       = a1;
        *(float4*)(op + (size_t)o1 * MPB + 128 + lane * 4) = b1;
        float s0 = (a0.x + a0.y + a0.z + a0.w) + (b0.x + b0.y + b0.z + b0.w);
        float q0 = (a0.x*a0.x + a0.y*a0.y + a0.z*a0.z + a0.w*a0.w)
                 + (b0.x*b0.x + b0.y*b0.y + b0.z*b0.z + b0.w*b0.w);
        float s1 = (a1.x + a1.y + a1.z + a1.w) + (b1.x + b1.y + b1.z + b1.w);
        float q1 = (a1.x*a1.x + a1.y*a1.y + a1.z*a1.z + a1.w*a1.w)
                 + (b1.x*b1.x + b1.y*b1.y + b1.z*b1.z + b1.w*b1.w);
#pragma unroll
        for (int off = 16; off; off >>= 1) {
            s0 += __shfl_xor_sync(0xffffffffu, s0, off);
            q0 += __shfl_xor_sync(0xffffffffu, q0, off);
            s1 += __shfl_xor_sync(0xffffffffu, s1, off);
            q1 += __shfl_xor_sync(0xffffffffu, q1, off);
        }
        if (lane == 0) {
            ps[o0 * NPB + pblk] = s0;  pq[o0 * NPB + pblk] = q0;
            ps[o1 * NPB + pblk] = s1;  pq[o1 * NPB + pblk] = q1;
        }
    }
}

// ------- conv+resid fused: stage x1 = relu(aff2(t2)+relu(aff0(y0))), conv it -------
// Replaces resid_kernel + conv<64,false>(x1). x1 written to global for finalmax;
// resid math is op-for-op identical to resid_kernel -> bit-identical x1.
__global__ __launch_bounds__(256) void conv_resid_kernel(const float* __restrict__ y0,
                                                         const float* __restrict__ t2,
                                                         const float* __restrict__ W,
                                                         const float* __restrict__ aff0,
                                                         const float* __restrict__ aff2,
                                                         float* __restrict__ x1,
                                                         float* __restrict__ out,
                                                         float* __restrict__ ps,
                                                         float* __restrict__ pq)
{
    constexpr int CIN = 64, CH = 8;
    __shared__ float sW[CIN][64];
    __shared__ float sX[2][8][256];
    __shared__ float sA0[64], sD0[64], sA2[64], sD2[64];
    int tid = threadIdx.x, lane = tid & 31, w = tid >> 5;
    int b = blockIdx.x >> 8, mblk = blockIdx.x & 255;
    size_t boff = (size_t)b * CIN * MPB + mblk * 256;
    const float* yp = y0 + boff;
    const float* tp = t2 + boff;
    float* xp = x1 + boff;

    for (int i = tid; i < CIN * 64; i += 256)
        sW[i >> 6][i & 63] = W[(i & 63) * CIN + (i >> 6)];
    for (int i = tid; i < 64; i += 256) {
        sA0[i] = aff0[i]; sD0[i] = aff0[64 + i];
        sA2[i] = aff2[i]; sD2[i] = aff2[64 + i];
    }
    __syncthreads();

    // stage channel ch into buffer buf: v = relu(aff2(t) + relu(aff0(y))), also
    // write v to global x1 (each (ch, m) element staged exactly once per grid)
    auto stage = [&](int ch, int buf) {
        float a0 = sA0[ch], d0 = sD0[ch], a2 = sA2[ch], d2 = sD2[ch];
        size_t co = (size_t)ch * MPB;
#pragma unroll
        for (int h = 0; h < 2; ++h) {
            int off = h * 128 + lane * 4;
            float4 y4 = *(const float4*)(yp + co + off);
            float4 t4 = *(const float4*)(tp + co + off);
            float4 v;
            v.x = fmaxf(fmaf(a2, t4.x, d2) + fmaxf(fmaf(a0, y4.x, d0), 0.f), 0.f);
            v.y = fmaxf(fmaf(a2, t4.y, d2) + fmaxf(fmaf(a0, y4.y, d0), 0.f), 0.f);
            v.z = fmaxf(fmaf(a2, t4.z, d2) + fmaxf(fmaf(a0, y4.z, d0), 0.f), 0.f);
            v.w = fmaxf(fmaf(a2, t4.w, d2) + fmaxf(fmaf(a0, y4.w, d0), 0.f), 0.f);
            *(float4*)&sX[buf][ch & 7][off] = v;
            *(float4*)(xp + co + off) = v;
        }
    };

    stage(w, 0);
    __syncthreads();

    int og = w * 8;
    unsigned long long acc[4][8];
#pragma unroll
    for (int p = 0; p < 4; ++p)
#pragma unroll
        for (int j = 0; j < 8; ++j) acc[p][j] = 0ull;

    for (int k = 0; k < CH; ++k) {
#pragma unroll
        for (int cc = 0; cc < 8; ++cc) {
            int c = k * 8 + cc;
            float4 ua = *(const float4*)&sX[k & 1][cc][lane * 4];
            float4 ub = *(const float4*)&sX[k & 1][cc][128 + lane * 4];
            unsigned long long xq[8] = { pk2(ua.x, ua.x), pk2(ua.y, ua.y),
                                         pk2(ua.z, ua.z), pk2(ua.w, ua.w),
                                         pk2(ub.x, ub.x), pk2(ub.y, ub.y),
                                         pk2(ub.z, ub.z), pk2(ub.w, ub.w) };
            const double2* wp = (const double2*)&sW[c][og];
            double2 w0 = wp[0], w1 = wp[1];
            unsigned long long wq[4] = {
                __double_as_longlong(w0.x), __double_as_longlong(w0.y),
                __double_as_longlong(w1.x), __double_as_longlong(w1.y) };
#pragma unroll
            for (int p = 0; p < 4; ++p)
#pragma unroll
                for (int j = 0; j < 8; ++j)
                    acc[p][j] = f2fma(wq[p], xq[j], acc[p][j]);
        }
        if (k + 1 < CH) stage((k + 1) * 8 + w, (k + 1) & 1);
        __syncthreads();
    }

    float* op = out + (size_t)b * 64 * MPB + mblk * 256;
    int pblk = b * 256 + mblk;
#pragma unroll
    for (int p = 0; p < 4; ++p) {
        float4 a0, a1, b0, b1;
        upk2(acc[p][0], a0.x, a1.x); upk2(acc[p][1], a0.y, a1.y);
        upk2(acc[p][2], a0.z, a1.z); upk2(acc[p][3], a0.w, a1.w);
        upk2(acc[p][4], b0.x, b1.x); upk2(acc[p][5], b0.y, b1.y);
        upk2(acc[p][6], b0.z, b1.z); upk2(acc[p][7], b0.w, b1.w);
        int o0 = og + 2*p, o1 = og + 2*p + 1;
        *(float4*)(op + (size_t)o0 * MPB + lane * 4)       = a0;
        *(float4*)(op + (size_t)o0 * MPB + 128 + lane * 4) = b0;
        *(float4*)(op + (size_t)o1 * MPB + lane * 4)       = a1;
        *(float4*)(op + (size_t)o1 * MPB + 128 + lane * 4) = b1;
        float s0 = (a0.x + a0.y + a0.z + a0.w) + (b0.x + b0.y + b0.z + b0.w);
        float q0 = (a0.x*a0.x + a0.y*a0.y + a0.z*a0.z + a0.w*a0.w)
                 + (b0.x*b0.x + b0.y*b0.y + b0.z*b0.z + b0.w*b0.w);
        float s1 = (a1.x + a1.y + a1.z + a1.w) + (b1.x + b1.y + b1.z + b1.w);
        float q1 = (a1.x*a1.x + a1.y*a1.y + a1.z*a1.z + a1.w*a1.w)
                 + (b1.x*b1.x + b1.y*b1.y + b1.z*b1.z + b1.w*b1.w);
#pragma unroll
        for (int off = 16; off; off >>= 1) {
            s0 += __shfl_xor_sync(0xffffffffu, s0, off);
            q0 += __shfl_xor_sync(0xffffffffu, q0, off);
            s1 += __shfl_xor_sync(0xffffffffu, s1, off);
            q1 += __shfl_xor_sync(0xffffffffu, q1, off);
        }
        if (lane == 0) {
            ps[o0 * NPB + pblk] = s0;  pq[o0 * NPB + pblk] = q0;
            ps[o1 * NPB + pblk] = s1;  pq[o1 * NPB + pblk] = q1;
        }
    }
}

// ---------------- stage-2 stats: NPB partials -> affine coeffs ----------------
__global__ __launch_bounds__(256) void statsfin2_kernel(const float* __restrict__ ps,
                                                        const float* __restrict__ pq,
                                                        const float* __restrict__ gam,
                                                        const float* __restrict__ bet,
                                                        float* __restrict__ aff)
{
    int o = blockIdx.x, tid = threadIdx.x;
    float s = 0.f, q = 0.f;
    for (int i = tid; i < NPB; i += 256) { s += ps[o*NPB + i]; q += pq[o*NPB + i]; }
    __shared__ float rs[256], rq[256];
    rs[tid] = s; rq[tid] = q;
    for (int off = 128; off; off >>= 1) {
        __syncthreads();
        if (tid < off) { rs[tid] += rs[tid + off]; rq[tid] += rq[tid + off]; }
    }
    if (tid == 0) {
        const float invn = 1.f / (float)(NB * MPB);
        float mean = rs[0] * invn;
        float var  = rq[0] * invn - mean * mean;
        float a = gam[o] * rsqrtf(var + 1e-5f);
        aff[o] = a;
        aff[64 + o] = bet[o] - a * mean;
    }
}

// ---------------- final: feat = max_k relu(aff4(t4) + x1) ----------------
__global__ __launch_bounds__(256) void finalmax_kernel(const float* __restrict__ t4,
                                                       const float* __restrict__ x1,
                                                       const float* __restrict__ aff,
                                                       float* __restrict__ outf)
{
    int g = blockIdx.x * 256 + threadIdx.x;
    int s = g & 2047, o = (g >> 11) & 63, b = g >> 17;
    float a = aff[o], d = aff[64 + o];
    size_t base = (size_t)(b*64 + o) * MPB + s;
    const float* tp = t4 + base;
    const float* xp = x1 + base;
    float m = -1e30f;
#pragma unroll 8
    for (int k = 0; k < 32; ++k)
        m = fmaxf(m, fmaf(a, tp[(size_t)k*2048], d) + xp[(size_t)k*2048]);
    outf[g] = fmaxf(m, 0.f);
}

extern "C" void kernel_launch(void* const* d_in, const int* in_sizes, int n_in,
                              void* d_out, int out_size)
{
    (void)in_sizes; (void)n_in; (void)out_size;
    const float* xyz = (const float*)d_in[0];
    const float* pts = (const float*)d_in[1];
    const float* pw  = (const float*)d_in[2];
    const float* pg  = (const float*)d_in[3];
    const float* pb  = (const float*)d_in[4];
    const float* w1  = (const float*)d_in[5];
    const float* g1  = (const float*)d_in[6];
    const float* b1  = (const float*)d_in[7];
    const float* w2  = (const float*)d_in[8];
    const float* g2  = (const float*)d_in[9];
    const float* b2  = (const float*)d_in[10];

    float *y0, *t1, *t2, *x1, *nx, *ps, *pq, *aff; int* gi;
    cudaGetSymbolAddress((void**)&y0,  g_y0);
    cudaGetSymbolAddress((void**)&t1,  g_t1);
    cudaGetSymbolAddress((void**)&t2,  g_t2);
    cudaGetSymbolAddress((void**)&x1,  g_x1);
    cudaGetSymbolAddress((void**)&nx,  g_nxyz);
    cudaGetSymbolAddress((void**)&gi,  g_idx);
    cudaGetSymbolAddress((void**)&ps,  g_ps);
    cudaGetSymbolAddress((void**)&pq,  g_pq);
    cudaGetSymbolAddress((void**)&aff, g_aff);
    float* out = (float*)d_out;

    cudaFuncSetAttribute(fps_kernel, cudaFuncAttributeMaxDynamicSharedMemorySize,
                         NPTS * (int)sizeof(float4));

    fps_kernel<<<NB * 8, 256, NPTS * sizeof(float4)>>>(xyz, out, nx);
    ball_kernel<<<1024, 256>>>(xyz, nx, gi);
    gather_kernel<<<1024, 256>>>(xyz, pts, gi, nx, t2);

    conv_kernel<32, false><<<1024, 256>>>(t2, pw, nullptr, y0, ps, pq);
    statsfin2_kernel<<<64, 256>>>(ps, pq, pg, pb, aff);

    conv_kernel<64, true><<<1024, 256>>>(y0, w1, aff, t1, ps, pq);
    statsfin2_kernel<<<64, 256>>>(ps, pq, g1, b1, aff + 128);

    conv_kernel<64, true><<<1024, 256>>>(t1, w2, aff + 128, t2, ps, pq);
    statsfin2_kernel<<<64, 256>>>(ps, pq, g2, b2, aff + 256);

    // fused resid + conv4: x1 materialized, t1 = w1[1] @ x1
    conv_resid_kernel<<<1024, 256>>>(y0, t2, w1 + 4096, aff, aff + 256, x1, t1, ps, pq);
    statsfin2_kernel<<<64, 256>>>(ps, pq, g1 + 64, b1 + 64, aff + 384);

    conv_kernel<64, true><<<1024, 256>>>(t1, w2 + 4096, aff + 384, t2, ps, pq);
    statsfin2_kernel<<<64, 256>>>(ps, pq, g2 + 64, b2 + 64, aff + 512);

    finalmax_kernel<<<2048, 256>>>(t2, x1, aff + 512, out + NB*3*NS);
}